// round 1
// baseline (speedup 1.0000x reference)
#include <cuda_runtime.h>
#include <math.h>

#define BB 2
#define SS 2048
#define DM 1024
#define DI 2048
#define DSTATE 16
#define RANK 64
#define MM (BB*SS)   /* 4096 rows (b,s) */

// ---------------- scratch (static device globals; no runtime allocation) ----------------
__device__ float g_xz[(size_t)MM * 2 * DI];     // [m][4096]  x@Win
__device__ float g_xbc[(size_t)MM * DI];        // conv+silu, [m][d]
__device__ float g_u[(size_t)BB * DI * SS];     // conv+silu, [b][d][s]
__device__ float g_params[(size_t)MM * 96];     // [m][96]  (delta_in | b | c)
__device__ float g_delta[(size_t)BB * DI * SS]; // softplus delta, [b][d][s]
__device__ float g_y[(size_t)MM * DI];          // scan output, [m][d]

// ---------------- GEMM1: g_xz = x @ Win  (M=4096,N=4096,K=1024) ----------------
__global__ __launch_bounds__(256, 2)
void gemm_xz_kernel(const float* __restrict__ A, const float* __restrict__ B)
{
    const int K = DM, N = 2 * DI;
    __shared__ float shA[8][132];
    __shared__ float shB[8][128];
    int tid = threadIdx.x;
    int m0 = blockIdx.y * 128;
    int n0 = blockIdx.x * 128;
    int arow = tid >> 1;            // 0..127
    int acol = (tid & 1) * 4;       // 0 or 4
    int brow = tid >> 5;            // 0..7
    int bcol = (tid & 31) * 4;
    int tx = tid & 15, ty = tid >> 4;

    float acc[8][8];
#pragma unroll
    for (int i = 0; i < 8; i++)
#pragma unroll
        for (int j = 0; j < 8; j++) acc[i][j] = 0.f;

    const float* Aptr = A + (size_t)(m0 + arow) * K + acol;
    const float* Bptr = B + (size_t)brow * N + n0 + bcol;

    for (int k0 = 0; k0 < K; k0 += 8) {
        float4 a4 = *(const float4*)Aptr;  Aptr += 8;
        float4 b4 = *(const float4*)Bptr;  Bptr += (size_t)8 * N;
        shA[acol + 0][arow] = a4.x;
        shA[acol + 1][arow] = a4.y;
        shA[acol + 2][arow] = a4.z;
        shA[acol + 3][arow] = a4.w;
        *(float4*)&shB[brow][bcol] = b4;
        __syncthreads();
#pragma unroll
        for (int kk = 0; kk < 8; kk++) {
            float4 ra0 = *(const float4*)&shA[kk][ty * 8];
            float4 ra1 = *(const float4*)&shA[kk][ty * 8 + 4];
            float4 rb0 = *(const float4*)&shB[kk][tx * 8];
            float4 rb1 = *(const float4*)&shB[kk][tx * 8 + 4];
            float ra[8] = {ra0.x, ra0.y, ra0.z, ra0.w, ra1.x, ra1.y, ra1.z, ra1.w};
            float rb[8] = {rb0.x, rb0.y, rb0.z, rb0.w, rb1.x, rb1.y, rb1.z, rb1.w};
#pragma unroll
            for (int i = 0; i < 8; i++)
#pragma unroll
                for (int j = 0; j < 8; j++)
                    acc[i][j] += ra[i] * rb[j];
        }
        __syncthreads();
    }
#pragma unroll
    for (int i = 0; i < 8; i++) {
        float* crow = g_xz + (size_t)(m0 + ty * 8 + i) * N + n0 + tx * 8;
        float4 v0 = {acc[i][0], acc[i][1], acc[i][2], acc[i][3]};
        float4 v1 = {acc[i][4], acc[i][5], acc[i][6], acc[i][7]};
        *(float4*)(crow)     = v0;
        *(float4*)(crow + 4) = v1;
    }
}

// ---------------- conv: depthwise causal K=4 + bias + silu; writes [m][d] and [b][d][s] ----------------
__global__ __launch_bounds__(256)
void conv_kernel(const float* __restrict__ Wconv, const float* __restrict__ bconv)
{
    __shared__ float sh_x[35][33];
    __shared__ float sh_o[32][33];
    __shared__ float sh_w[4][32];
    __shared__ float sh_b[32];
    int tid = threadIdx.x;
    int b  = blockIdx.z;
    int d0 = blockIdx.y * 32;
    int s0 = blockIdx.x * 32;

    for (int idx = tid; idx < 35 * 32; idx += 256) {
        int r = idx >> 5, c = idx & 31;
        int s = s0 - 3 + r;
        float v = 0.f;
        if (s >= 0)
            v = g_xz[((size_t)(b * SS + s)) * (2 * DI) + d0 + c];
        sh_x[r][c] = v;
    }
    if (tid < 128) {
        int k = tid >> 5, c = tid & 31;
        sh_w[k][c] = Wconv[(size_t)(d0 + c) * 4 + k];
    }
    if (tid < 32) sh_b[tid] = bconv[d0 + tid];
    __syncthreads();

    int td = tid & 31, tg = tid >> 5;   // tg 0..7
#pragma unroll
    for (int si = 0; si < 4; si++) {
        int ss = tg + si * 8;
        float o = sh_b[td]
                + sh_x[ss + 0][td] * sh_w[0][td]
                + sh_x[ss + 1][td] * sh_w[1][td]
                + sh_x[ss + 2][td] * sh_w[2][td]
                + sh_x[ss + 3][td] * sh_w[3][td];
        o = o / (1.f + __expf(-o));                 // silu
        sh_o[ss][td] = o;
        g_xbc[((size_t)(b * SS + s0 + ss)) * DI + d0 + td] = o;
    }
    __syncthreads();
#pragma unroll
    for (int di = 0; di < 4; di++) {
        int dd = tg + di * 8;
        g_u[((size_t)(b * DI + d0 + dd)) * SS + s0 + td] = sh_o[td][dd];
    }
}

// ---------------- GEMM2: g_params = g_xbc @ Wx  (M=4096,N=96,K=2048) ----------------
__global__ __launch_bounds__(256)
void gemm_params_kernel(const float* __restrict__ Wx)
{
    __shared__ float shA[16][68];
    __shared__ float shB[16][96];
    int tid = threadIdx.x;
    int m0 = blockIdx.x * 64;
    int tx = tid & 15, ty = tid >> 4;     // tx: col group (6), ty: row group (4)

    float acc[4][6];
#pragma unroll
    for (int i = 0; i < 4; i++)
#pragma unroll
        for (int j = 0; j < 6; j++) acc[i][j] = 0.f;

    int ar = tid >> 2;            // 0..63
    int ac = (tid & 3) * 4;       // 0,4,8,12

    for (int k0 = 0; k0 < DI; k0 += 16) {
        float4 a4 = *(const float4*)&g_xbc[(size_t)(m0 + ar) * DI + k0 + ac];
        shA[ac + 0][ar] = a4.x;
        shA[ac + 1][ar] = a4.y;
        shA[ac + 2][ar] = a4.z;
        shA[ac + 3][ar] = a4.w;
#pragma unroll
        for (int t = 0; t < 6; t++) {
            int idx = tid + t * 256;   // < 1536
            int r = idx / 96, c = idx % 96;
            shB[r][c] = Wx[(size_t)(k0 + r) * 96 + c];
        }
        __syncthreads();
#pragma unroll
        for (int kk = 0; kk < 16; kk++) {
            float ra[4], rb[6];
#pragma unroll
            for (int i = 0; i < 4; i++) ra[i] = shA[kk][ty * 4 + i];
#pragma unroll
            for (int j = 0; j < 6; j++) rb[j] = shB[kk][tx * 6 + j];
#pragma unroll
            for (int i = 0; i < 4; i++)
#pragma unroll
                for (int j = 0; j < 6; j++)
                    acc[i][j] += ra[i] * rb[j];
        }
        __syncthreads();
    }
#pragma unroll
    for (int i = 0; i < 4; i++)
#pragma unroll
        for (int j = 0; j < 6; j++)
            g_params[(size_t)(m0 + ty * 4 + i) * 96 + tx * 6 + j] = acc[i][j];
}

// ---------------- delta GEMM: softplus(delta_in @ Wdt + bdt) -> g_delta[b][d][s] ----------------
__global__ __launch_bounds__(256)
void gemm_delta_kernel(const float* __restrict__ Wdt, const float* __restrict__ bdt)
{
    __shared__ float shA[32][65];   // [s][k]
    __shared__ float shB[64][64];   // [k][d]
    int tid = threadIdx.x;
    int m0 = blockIdx.x * 32;       // row tile (b,s combined)
    int dn0 = blockIdx.y * 64;      // d tile

#pragma unroll
    for (int t = 0; t < 8; t++) {
        int idx = tid + t * 256;    // < 2048
        int r = idx >> 6, c = idx & 63;
        shA[r][c] = g_params[(size_t)(m0 + r) * 96 + c];
    }
#pragma unroll
    for (int t = 0; t < 16; t++) {
        int idx = tid + t * 256;    // < 4096
        int r = idx >> 6, c = idx & 63;
        shB[r][c] = Wdt[(size_t)r * DI + dn0 + c];
    }
    __syncthreads();

    int s_loc = tid & 31;
    int dgrp = tid >> 5;            // 0..7
    float acc[8];
#pragma unroll
    for (int j = 0; j < 8; j++) acc[j] = 0.f;

#pragma unroll 8
    for (int k = 0; k < 64; k++) {
        float av = shA[s_loc][k];
        float4 b0 = *(const float4*)&shB[k][dgrp * 8];
        float4 b1 = *(const float4*)&shB[k][dgrp * 8 + 4];
        acc[0] += av * b0.x; acc[1] += av * b0.y;
        acc[2] += av * b0.z; acc[3] += av * b0.w;
        acc[4] += av * b1.x; acc[5] += av * b1.y;
        acc[6] += av * b1.z; acc[7] += av * b1.w;
    }

    int m = m0 + s_loc;
    int b = m >> 11;          // /2048
    int s = m & 2047;
#pragma unroll
    for (int j = 0; j < 8; j++) {
        int d = dn0 + dgrp * 8 + j;
        float t = acc[j] + bdt[d];
        float sp = fmaxf(t, 0.f) + log1pf(__expf(-fabsf(t)));   // stable softplus
        g_delta[((size_t)(b * DI + d)) * SS + s] = sp;
    }
}

// ---------------- selective scan: lane = 4 states, 8 channels/warp ----------------
__global__ __launch_bounds__(64, 8)
void scan_kernel(const float* __restrict__ A_log, const float* __restrict__ Dp)
{
    __shared__ float sh_d[16][33];
    __shared__ float sh_u[16][33];
    __shared__ float sh_bc[32][32];
    int tid = threadIdx.x;
    int lane = tid & 31, w = tid >> 5;       // w 0..1
    int gch0 = blockIdx.x * 16;
    int b  = gch0 / DI;
    int d0 = gch0 % DI;
    int chw = lane >> 2;                      // 0..7 channel within warp
    int q = lane & 3;                         // state quad
    int d = d0 + w * 8 + chw;

    float a0, a1, a2, a3;
    {
        float4 al = *(const float4*)&A_log[(size_t)d * DSTATE + q * 4];
        a0 = -__expf(al.x); a1 = -__expf(al.y);
        a2 = -__expf(al.z); a3 = -__expf(al.w);
    }
    float dpv = Dp[d];
    float s0 = 0.f, s1 = 0.f, s2 = 0.f, s3 = 0.f;

    const float* dbase = g_delta + (size_t)(b * DI + d0) * SS;
    const float* ubase = g_u     + (size_t)(b * DI + d0) * SS;
    const float* pbase = g_params + (size_t)b * SS * 96 + 64;
    float* ybase = g_y + (size_t)b * SS * DI + d0;

    int ch = w * 8 + chw;

    for (int t0 = 0; t0 < SS; t0 += 32) {
#pragma unroll
        for (int r = 0; r < 8; r++) {
            int cc = w * 8 + r;
            sh_d[cc][lane] = dbase[(size_t)cc * SS + t0 + lane];
            sh_u[cc][lane] = ubase[(size_t)cc * SS + t0 + lane];
        }
#pragma unroll
        for (int t = 0; t < 16; t++) {
            int idx = tid + t * 64;
            int i = idx >> 5, j = idx & 31;
            sh_bc[i][j] = pbase[(size_t)(t0 + i) * 96 + j];
        }
        __syncthreads();
#pragma unroll 4
        for (int i = 0; i < 32; i++) {
            float dlt = sh_d[ch][i];
            float uu  = sh_u[ch][i];
            float du  = dlt * uu;
            float4 b4 = *(const float4*)&sh_bc[i][q * 4];
            float4 c4 = *(const float4*)&sh_bc[i][16 + q * 4];
            float e0 = __expf(dlt * a0);
            float e1 = __expf(dlt * a1);
            float e2 = __expf(dlt * a2);
            float e3 = __expf(dlt * a3);
            s0 = e0 * s0 + du * b4.x;
            s1 = e1 * s1 + du * b4.y;
            s2 = e2 * s2 + du * b4.z;
            s3 = e3 * s3 + du * b4.w;
            float acc = s0 * c4.x + s1 * c4.y + s2 * c4.z + s3 * c4.w;
            acc += __shfl_xor_sync(0xffffffffu, acc, 1);
            acc += __shfl_xor_sync(0xffffffffu, acc, 2);
            if (q == 0)
                ybase[(size_t)(t0 + i) * DI + w * 8 + chw] = acc + uu * dpv;
        }
        __syncthreads();
    }
}

// ---------------- GEMM3: out = (g_y * silu(z)) @ Wout  (M=4096,N=1024,K=2048) ----------------
__global__ __launch_bounds__(256, 2)
void gemm_out_kernel(const float* __restrict__ Wout, float* __restrict__ C)
{
    const int K = DI, N = DM;
    __shared__ float shA[8][132];
    __shared__ float shB[8][128];
    int tid = threadIdx.x;
    int m0 = blockIdx.y * 128;
    int n0 = blockIdx.x * 128;
    int arow = tid >> 1;
    int acol = (tid & 1) * 4;
    int brow = tid >> 5;
    int bcol = (tid & 31) * 4;
    int tx = tid & 15, ty = tid >> 4;

    float acc[8][8];
#pragma unroll
    for (int i = 0; i < 8; i++)
#pragma unroll
        for (int j = 0; j < 8; j++) acc[i][j] = 0.f;

    const float* Yptr = g_y + (size_t)(m0 + arow) * DI + acol;
    const float* Zptr = g_xz + (size_t)(m0 + arow) * (2 * DI) + DI + acol;  // z branch
    const float* Bptr = Wout + (size_t)brow * N + n0 + bcol;

    for (int k0 = 0; k0 < K; k0 += 8) {
        float4 y4 = *(const float4*)Yptr;  Yptr += 8;
        float4 z4 = *(const float4*)Zptr;  Zptr += 8;
        float4 b4 = *(const float4*)Bptr;  Bptr += (size_t)8 * N;
        float ax = y4.x * z4.x / (1.f + __expf(-z4.x));
        float ay = y4.y * z4.y / (1.f + __expf(-z4.y));
        float az = y4.z * z4.z / (1.f + __expf(-z4.z));
        float aw = y4.w * z4.w / (1.f + __expf(-z4.w));
        shA[acol + 0][arow] = ax;
        shA[acol + 1][arow] = ay;
        shA[acol + 2][arow] = az;
        shA[acol + 3][arow] = aw;
        *(float4*)&shB[brow][bcol] = b4;
        __syncthreads();
#pragma unroll
        for (int kk = 0; kk < 8; kk++) {
            float4 ra0 = *(const float4*)&shA[kk][ty * 8];
            float4 ra1 = *(const float4*)&shA[kk][ty * 8 + 4];
            float4 rb0 = *(const float4*)&shB[kk][tx * 8];
            float4 rb1 = *(const float4*)&shB[kk][tx * 8 + 4];
            float ra[8] = {ra0.x, ra0.y, ra0.z, ra0.w, ra1.x, ra1.y, ra1.z, ra1.w};
            float rb[8] = {rb0.x, rb0.y, rb0.z, rb0.w, rb1.x, rb1.y, rb1.z, rb1.w};
#pragma unroll
            for (int i = 0; i < 8; i++)
#pragma unroll
                for (int j = 0; j < 8; j++)
                    acc[i][j] += ra[i] * rb[j];
        }
        __syncthreads();
    }
#pragma unroll
    for (int i = 0; i < 8; i++) {
        float* crow = C + (size_t)(m0 + ty * 8 + i) * N + n0 + tx * 8;
        float4 v0 = {acc[i][0], acc[i][1], acc[i][2], acc[i][3]};
        float4 v1 = {acc[i][4], acc[i][5], acc[i][6], acc[i][7]};
        *(float4*)(crow)     = v0;
        *(float4*)(crow + 4) = v1;
    }
}

// ---------------- launch ----------------
extern "C" void kernel_launch(void* const* d_in, const int* in_sizes, int n_in,
                              void* d_out, int out_size)
{
    (void)in_sizes; (void)n_in; (void)out_size;
    const float* x     = (const float*)d_in[0];
    const float* Win   = (const float*)d_in[1];
    const float* Wconv = (const float*)d_in[2];
    const float* bconv = (const float*)d_in[3];
    const float* Wx    = (const float*)d_in[4];
    const float* Wdt   = (const float*)d_in[5];
    const float* bdt   = (const float*)d_in[6];
    const float* A_log = (const float*)d_in[7];
    const float* Dp    = (const float*)d_in[8];
    const float* Wout  = (const float*)d_in[9];
    float* out = (float*)d_out;

    gemm_xz_kernel<<<dim3(32, 32), 256>>>(x, Win);
    conv_kernel<<<dim3(SS / 32, DI / 32, BB), 256>>>(Wconv, bconv);
    gemm_params_kernel<<<dim3(MM / 64), 256>>>(Wx);
    gemm_delta_kernel<<<dim3(MM / 32, DI / 64), 256>>>(Wdt, bdt);
    scan_kernel<<<dim3(MM * DI / (SS * 16) * (SS / SS) * 0 + (BB * DI / 16)), 64>>>(A_log, Dp);
    gemm_out_kernel<<<dim3(DM / 128, MM / 128), 256>>>(Wout, out);
}

// round 3
// speedup vs baseline: 1.8118x; 1.8118x over previous
#include <cuda_runtime.h>
#include <cuda_bf16.h>
#include <math.h>
#include <stdint.h>

#define BB 2
#define SS 2048
#define DM 1024
#define DI 2048
#define DSTATE 16
#define RANK 64
#define MM (BB*SS)   /* 4096 rows (b,s) */

// ---------------- scratch (static device globals; no runtime allocation) ----------------
__device__ float g_xz[(size_t)MM * 2 * DI];     // [m][4096]  x@Win
__device__ float g_xbc[(size_t)MM * DI];        // conv+silu, [m][d]
__device__ float g_u[(size_t)BB * DI * SS];     // conv+silu, [b][d][s]
__device__ float g_params[(size_t)MM * 96];     // [m][96]  (delta_in | b | c)
__device__ float g_delta[(size_t)BB * DI * SS]; // softplus delta, [b][d][s]
__device__ float g_y[(size_t)MM * DI];          // scan output, [m][d]

// bf16 split operands for tensor-core GEMMs
__device__ __nv_bfloat16 g_A1h[(size_t)MM * DM];
__device__ __nv_bfloat16 g_A1l[(size_t)MM * DM];
__device__ __nv_bfloat16 g_B1h[(size_t)(2*DI) * DM];   // Win^T [N=4096][K=1024]
__device__ __nv_bfloat16 g_B1l[(size_t)(2*DI) * DM];
__device__ __nv_bfloat16 g_A3h[(size_t)MM * DI];       // gated y [4096][2048]
__device__ __nv_bfloat16 g_A3l[(size_t)MM * DI];
__device__ __nv_bfloat16 g_B3h[(size_t)DM * DI];       // Wout^T [N=1024][K=2048]
__device__ __nv_bfloat16 g_B3l[(size_t)DM * DI];

// ================= low-level helpers (baseline PTX only: sm_80-class) =================
__device__ __forceinline__ uint32_t smem_to_u32(const void* smem_ptr) {
    uint32_t addr;
    asm("{ .reg .u64 tmp; cvta.to.shared.u64 tmp, %1; cvt.u32.u64 %0, tmp; }"
        : "=r"(addr) : "l"(smem_ptr));
    return addr;
}
#define CP_ASYNC16(saddr, gaddr) \
    asm volatile("cp.async.cg.shared.global [%0], [%1], 16;" :: "r"(saddr), "l"(gaddr))
#define CP_COMMIT() asm volatile("cp.async.commit_group;" ::: "memory")
#define CP_WAIT(n)  asm volatile("cp.async.wait_group %0;" :: "n"(n) : "memory")

__device__ __forceinline__ void ldsm4(uint32_t* r, uint32_t addr) {
    asm volatile("ldmatrix.sync.aligned.m8n8.x4.shared.b16 {%0,%1,%2,%3}, [%4];"
        : "=r"(r[0]), "=r"(r[1]), "=r"(r[2]), "=r"(r[3]) : "r"(addr));
}
__device__ __forceinline__ void mma16816(float* d, const uint32_t* a, const uint32_t* b) {
    asm volatile(
        "mma.sync.aligned.m16n8k16.row.col.f32.bf16.bf16.f32 "
        "{%0,%1,%2,%3}, {%4,%5,%6,%7}, {%8,%9}, {%0,%1,%2,%3};"
        : "+f"(d[0]), "+f"(d[1]), "+f"(d[2]), "+f"(d[3])
        : "r"(a[0]), "r"(a[1]), "r"(a[2]), "r"(a[3]), "r"(b[0]), "r"(b[1]));
}

// ================= split / transpose kernels =================
__device__ __forceinline__ void split1(float v, unsigned short& h, unsigned short& l) {
    __nv_bfloat16 hb = __float2bfloat16_rn(v);
    float r = v - __bfloat162float(hb);
    __nv_bfloat16 lb = __float2bfloat16_rn(r);
    h = __bfloat16_as_ushort(hb);
    l = __bfloat16_as_ushort(lb);
}

__global__ void split_x_kernel(const float* __restrict__ src)   // -> g_A1h/l
{
    int i = blockIdx.x * 256 + threadIdx.x;   // 1M float4
    float4 v = ((const float4*)src)[i];
    unsigned short h0,h1,h2,h3,l0,l1,l2,l3;
    split1(v.x,h0,l0); split1(v.y,h1,l1); split1(v.z,h2,l2); split1(v.w,h3,l3);
    uint2 ph = make_uint2((uint32_t)h0 | ((uint32_t)h1<<16), (uint32_t)h2 | ((uint32_t)h3<<16));
    uint2 pl = make_uint2((uint32_t)l0 | ((uint32_t)l1<<16), (uint32_t)l2 | ((uint32_t)l3<<16));
    *(uint2*)&g_A1h[(size_t)i*4] = ph;
    *(uint2*)&g_A1l[(size_t)i*4] = pl;
}

__global__ void gate_split_kernel()   // A3 = g_y * silu(z) -> g_A3h/l
{
    int i = blockIdx.x * 256 + threadIdx.x;   // 2M float4
    int e = i * 4;
    int m = e >> 11;          // /2048
    int k = e & 2047;
    float4 y4 = *(const float4*)&g_y[(size_t)m * DI + k];
    float4 z4 = *(const float4*)&g_xz[(size_t)m * (2*DI) + DI + k];
    float a0 = y4.x * z4.x / (1.f + __expf(-z4.x));
    float a1 = y4.y * z4.y / (1.f + __expf(-z4.y));
    float a2 = y4.z * z4.z / (1.f + __expf(-z4.z));
    float a3 = y4.w * z4.w / (1.f + __expf(-z4.w));
    unsigned short h0,h1,h2,h3,l0,l1,l2,l3;
    split1(a0,h0,l0); split1(a1,h1,l1); split1(a2,h2,l2); split1(a3,h3,l3);
    uint2 ph = make_uint2((uint32_t)h0 | ((uint32_t)h1<<16), (uint32_t)h2 | ((uint32_t)h3<<16));
    uint2 pl = make_uint2((uint32_t)l0 | ((uint32_t)l1<<16), (uint32_t)l2 | ((uint32_t)l3<<16));
    *(uint2*)&g_A3h[(size_t)e] = ph;
    *(uint2*)&g_A3l[(size_t)e] = pl;
}

// WHICH=1: Win [1024][4096] -> g_B1h/l [4096][1024]
// WHICH=3: Wout [2048][1024] -> g_B3h/l [1024][2048]
template<int WHICH>
__global__ void transpose_split_kernel(const float* __restrict__ src)
{
    constexpr int KD = (WHICH == 1) ? DM : DI;       // dst inner dim (K)
    constexpr int ND = (WHICH == 1) ? 2*DI : DM;     // dst outer dim (N)
    __nv_bfloat16* dh = (WHICH == 1) ? g_B1h : g_B3h;
    __nv_bfloat16* dl = (WHICH == 1) ? g_B1l : g_B3l;
    __shared__ float t[32][33];
    int n0 = blockIdx.x * 32, k0 = blockIdx.y * 32;
    int tx = threadIdx.x, ty = threadIdx.y;
#pragma unroll
    for (int i = 0; i < 4; i++)
        t[ty + i*8][tx] = src[(size_t)(k0 + ty + i*8) * ND + n0 + tx];
    __syncthreads();
#pragma unroll
    for (int i = 0; i < 4; i++) {
        int n = n0 + ty + i*8, k = k0 + tx;
        float v = t[tx][ty + i*8];
        unsigned short h, l;
        split1(v, h, l);
        dh[(size_t)n * KD + k] = __ushort_as_bfloat16(h);
        dl[(size_t)n * KD + k] = __ushort_as_bfloat16(l);
    }
}

// ================= mma.sync GEMM: C[4096][N] = A @ B^T (3x bf16 split) =================
// Block tile 128x128, 8 warps (warp tile 32m x 64n), K-chunk 32, cp.async double buffer.
static constexpr int TSTRIDE = 40;                        // padded row stride (bf16 elems)
static constexpr uint32_t TILE_B = 128 * TSTRIDE * 2;     // 10240 B per tile
static constexpr uint32_t STAGE_B = 4 * TILE_B;           // Ah Al Bh Bl
static constexpr uint32_t GSMEM_B = 2 * STAGE_B;          // 81920 B

__device__ __forceinline__ void load_tile_ca(uint32_t sbase, const __nv_bfloat16* g,
                                             int row0, int ktot, int kbase, int tid)
{
#pragma unroll
    for (int it = 0; it < 2; it++) {
        int u = tid + it * 256;            // 0..511
        int r = u >> 2, seg = u & 3;
        uint32_t s = sbase + (uint32_t)(r * TSTRIDE + seg * 8) * 2;
        const __nv_bfloat16* gp = g + (size_t)(row0 + r) * ktot + kbase + seg * 8;
        CP_ASYNC16(s, gp);
    }
}

template<int WHICH>
__global__ __launch_bounds__(256, 1)
void mma_gemm_kernel(float* __restrict__ Cout)
{
    constexpr int KTOT = (WHICH == 1) ? DM : DI;
    constexpr int NC = KTOT / 32;
    constexpr int LDC = (WHICH == 1) ? (2*DI) : DM;
    const __nv_bfloat16* Ah = (WHICH == 1) ? g_A1h : g_A3h;
    const __nv_bfloat16* Al = (WHICH == 1) ? g_A1l : g_A3l;
    const __nv_bfloat16* Bh = (WHICH == 1) ? g_B1h : g_B3h;
    const __nv_bfloat16* Bl = (WHICH == 1) ? g_B1l : g_B3l;

    extern __shared__ __align__(16) char smem[];
    uint32_t sb = smem_to_u32(smem);

    int tid = threadIdx.x;
    int lane = tid & 31, wid = tid >> 5;
    int wm = wid & 3;          // 0..3 -> 32-row slice
    int wn = wid >> 2;         // 0..1 -> 64-col slice
    int m0 = blockIdx.y * 128;
    int n0 = blockIdx.x * 128;

    float d[2][8][4];
#pragma unroll
    for (int mt = 0; mt < 2; mt++)
#pragma unroll
        for (int nt = 0; nt < 8; nt++)
#pragma unroll
            for (int i = 0; i < 4; i++) d[mt][nt][i] = 0.f;

    // stage layout offsets (bytes)
    const uint32_t OA_H = 0, OA_L = TILE_B, OB_H = 2*TILE_B, OB_L = 3*TILE_B;

    // prologue: stage 0
    {
        uint32_t base = sb;
        load_tile_ca(base + OA_H, Ah, m0, KTOT, 0, tid);
        load_tile_ca(base + OA_L, Al, m0, KTOT, 0, tid);
        load_tile_ca(base + OB_H, Bh, n0, KTOT, 0, tid);
        load_tile_ca(base + OB_L, Bl, n0, KTOT, 0, tid);
        CP_COMMIT();
    }

    int quad = lane >> 3, lrow = lane & 7;

    for (int kc = 0; kc < NC; kc++) {
        if (kc + 1 < NC) {
            uint32_t base = sb + ((kc + 1) & 1) * STAGE_B;
            int kb = (kc + 1) * 32;
            load_tile_ca(base + OA_H, Ah, m0, KTOT, kb, tid);
            load_tile_ca(base + OA_L, Al, m0, KTOT, kb, tid);
            load_tile_ca(base + OB_H, Bh, n0, KTOT, kb, tid);
            load_tile_ca(base + OB_L, Bl, n0, KTOT, kb, tid);
            CP_COMMIT();
            CP_WAIT(1);
        } else {
            CP_WAIT(0);
        }
        __syncthreads();

        uint32_t base = sb + (kc & 1) * STAGE_B;
#pragma unroll
        for (int ks = 0; ks < 2; ks++) {
            int k16 = ks * 16;
            uint32_t aH[2][4], aL[2][4];
#pragma unroll
            for (int mt = 0; mt < 2; mt++) {
                int row = wm * 32 + mt * 16 + (quad & 1) * 8 + lrow;
                uint32_t off = (uint32_t)(row * TSTRIDE + k16 + (quad >> 1) * 8) * 2;
                ldsm4(aH[mt], base + OA_H + off);
                ldsm4(aL[mt], base + OA_L + off);
            }
            uint32_t bH[8][2], bL[8][2];
#pragma unroll
            for (int np = 0; np < 4; np++) {
                int nrow = wn * 64 + np * 16 + (quad >> 1) * 8 + lrow;
                uint32_t off = (uint32_t)(nrow * TSTRIDE + k16 + (quad & 1) * 8) * 2;
                uint32_t t[4];
                ldsm4(t, base + OB_H + off);
                bH[np*2][0] = t[0]; bH[np*2][1] = t[1];
                bH[np*2+1][0] = t[2]; bH[np*2+1][1] = t[3];
                ldsm4(t, base + OB_L + off);
                bL[np*2][0] = t[0]; bL[np*2][1] = t[1];
                bL[np*2+1][0] = t[2]; bL[np*2+1][1] = t[3];
            }
#pragma unroll
            for (int mt = 0; mt < 2; mt++)
#pragma unroll
                for (int nt = 0; nt < 8; nt++) {
                    mma16816(d[mt][nt], aH[mt], bH[nt]);
                    mma16816(d[mt][nt], aH[mt], bL[nt]);
                    mma16816(d[mt][nt], aL[mt], bH[nt]);
                }
        }
        __syncthreads();
    }

    float* C = (WHICH == 1) ? g_xz : Cout;
#pragma unroll
    for (int mt = 0; mt < 2; mt++)
#pragma unroll
        for (int nt = 0; nt < 8; nt++) {
            int row = m0 + wm * 32 + mt * 16 + (lane >> 2);
            int col = n0 + wn * 64 + nt * 8 + (lane & 3) * 2;
            float2 v0 = {d[mt][nt][0], d[mt][nt][1]};
            float2 v1 = {d[mt][nt][2], d[mt][nt][3]};
            *(float2*)&C[(size_t)row * LDC + col] = v0;
            *(float2*)&C[(size_t)(row + 8) * LDC + col] = v1;
        }
}

// ---------------- conv: depthwise causal K=4 + bias + silu ----------------
__global__ __launch_bounds__(256)
void conv_kernel(const float* __restrict__ Wconv, const float* __restrict__ bconv)
{
    __shared__ float sh_x[35][33];
    __shared__ float sh_o[32][33];
    __shared__ float sh_w[4][32];
    __shared__ float sh_b[32];
    int tid = threadIdx.x;
    int b  = blockIdx.z;
    int d0 = blockIdx.y * 32;
    int s0 = blockIdx.x * 32;

    for (int idx = tid; idx < 35 * 32; idx += 256) {
        int r = idx >> 5, c = idx & 31;
        int s = s0 - 3 + r;
        float v = 0.f;
        if (s >= 0)
            v = g_xz[((size_t)(b * SS + s)) * (2 * DI) + d0 + c];
        sh_x[r][c] = v;
    }
    if (tid < 128) {
        int k = tid >> 5, c = tid & 31;
        sh_w[k][c] = Wconv[(size_t)(d0 + c) * 4 + k];
    }
    if (tid < 32) sh_b[tid] = bconv[d0 + tid];
    __syncthreads();

    int td = tid & 31, tg = tid >> 5;
#pragma unroll
    for (int si = 0; si < 4; si++) {
        int ss = tg + si * 8;
        float o = sh_b[td]
                + sh_x[ss + 0][td] * sh_w[0][td]
                + sh_x[ss + 1][td] * sh_w[1][td]
                + sh_x[ss + 2][td] * sh_w[2][td]
                + sh_x[ss + 3][td] * sh_w[3][td];
        o = o / (1.f + __expf(-o));
        sh_o[ss][td] = o;
        g_xbc[((size_t)(b * SS + s0 + ss)) * DI + d0 + td] = o;
    }
    __syncthreads();
#pragma unroll
    for (int di = 0; di < 4; di++) {
        int dd = tg + di * 8;
        g_u[((size_t)(b * DI + d0 + dd)) * SS + s0 + td] = sh_o[td][dd];
    }
}

// ---------------- GEMM2: g_params = g_xbc @ Wx ----------------
__global__ __launch_bounds__(256)
void gemm_params_kernel(const float* __restrict__ Wx)
{
    __shared__ float shA[16][68];
    __shared__ float shB[16][96];
    int tid = threadIdx.x;
    int m0 = blockIdx.x * 64;
    int tx = tid & 15, ty = tid >> 4;

    float acc[4][6];
#pragma unroll
    for (int i = 0; i < 4; i++)
#pragma unroll
        for (int j = 0; j < 6; j++) acc[i][j] = 0.f;

    int ar = tid >> 2;
    int ac = (tid & 3) * 4;

    for (int k0 = 0; k0 < DI; k0 += 16) {
        float4 a4 = *(const float4*)&g_xbc[(size_t)(m0 + ar) * DI + k0 + ac];
        shA[ac + 0][ar] = a4.x;
        shA[ac + 1][ar] = a4.y;
        shA[ac + 2][ar] = a4.z;
        shA[ac + 3][ar] = a4.w;
#pragma unroll
        for (int t = 0; t < 6; t++) {
            int idx = tid + t * 256;
            int r = idx / 96, c = idx % 96;
            shB[r][c] = Wx[(size_t)(k0 + r) * 96 + c];
        }
        __syncthreads();
#pragma unroll
        for (int kk = 0; kk < 16; kk++) {
            float ra[4], rb[6];
#pragma unroll
            for (int i = 0; i < 4; i++) ra[i] = shA[kk][ty * 4 + i];
#pragma unroll
            for (int j = 0; j < 6; j++) rb[j] = shB[kk][tx * 6 + j];
#pragma unroll
            for (int i = 0; i < 4; i++)
#pragma unroll
                for (int j = 0; j < 6; j++)
                    acc[i][j] += ra[i] * rb[j];
        }
        __syncthreads();
    }
#pragma unroll
    for (int i = 0; i < 4; i++)
#pragma unroll
        for (int j = 0; j < 6; j++)
            g_params[(size_t)(m0 + ty * 4 + i) * 96 + tx * 6 + j] = acc[i][j];
}

// ---------------- delta GEMM: softplus(delta_in @ Wdt + bdt) ----------------
__global__ __launch_bounds__(256)
void gemm_delta_kernel(const float* __restrict__ Wdt, const float* __restrict__ bdt)
{
    __shared__ float shA[32][65];
    __shared__ float shB[64][64];
    int tid = threadIdx.x;
    int m0 = blockIdx.x * 32;
    int dn0 = blockIdx.y * 64;

#pragma unroll
    for (int t = 0; t < 8; t++) {
        int idx = tid + t * 256;
        int r = idx >> 6, c = idx & 63;
        shA[r][c] = g_params[(size_t)(m0 + r) * 96 + c];
    }
#pragma unroll
    for (int t = 0; t < 16; t++) {
        int idx = tid + t * 256;
        int r = idx >> 6, c = idx & 63;
        shB[r][c] = Wdt[(size_t)r * DI + dn0 + c];
    }
    __syncthreads();

    int s_loc = tid & 31;
    int dgrp = tid >> 5;
    float acc[8];
#pragma unroll
    for (int j = 0; j < 8; j++) acc[j] = 0.f;

#pragma unroll 8
    for (int k = 0; k < 64; k++) {
        float av = shA[s_loc][k];
        float4 b0 = *(const float4*)&shB[k][dgrp * 8];
        float4 b1 = *(const float4*)&shB[k][dgrp * 8 + 4];
        acc[0] += av * b0.x; acc[1] += av * b0.y;
        acc[2] += av * b0.z; acc[3] += av * b0.w;
        acc[4] += av * b1.x; acc[5] += av * b1.y;
        acc[6] += av * b1.z; acc[7] += av * b1.w;
    }

    int m = m0 + s_loc;
    int b = m >> 11;
    int s = m & 2047;
#pragma unroll
    for (int j = 0; j < 8; j++) {
        int d = dn0 + dgrp * 8 + j;
        float t = acc[j] + bdt[d];
        float sp = fmaxf(t, 0.f) + log1pf(__expf(-fabsf(t)));
        g_delta[((size_t)(b * DI + d)) * SS + s] = sp;
    }
}

// ---------------- selective scan ----------------
__global__ __launch_bounds__(64, 8)
void scan_kernel(const float* __restrict__ A_log, const float* __restrict__ Dp)
{
    __shared__ float sh_d[16][33];
    __shared__ float sh_u[16][33];
    __shared__ float sh_bc[32][32];
    int tid = threadIdx.x;
    int lane = tid & 31, w = tid >> 5;
    int gch0 = blockIdx.x * 16;
    int b  = gch0 / DI;
    int d0 = gch0 % DI;
    int chw = lane >> 2;
    int q = lane & 3;
    int d = d0 + w * 8 + chw;

    float a0, a1, a2, a3;
    {
        float4 al = *(const float4*)&A_log[(size_t)d * DSTATE + q * 4];
        a0 = -__expf(al.x); a1 = -__expf(al.y);
        a2 = -__expf(al.z); a3 = -__expf(al.w);
    }
    float dpv = Dp[d];
    float s0 = 0.f, s1 = 0.f, s2 = 0.f, s3 = 0.f;

    const float* dbase = g_delta + (size_t)(b * DI + d0) * SS;
    const float* ubase = g_u     + (size_t)(b * DI + d0) * SS;
    const float* pbase = g_params + (size_t)b * SS * 96 + 64;
    float* ybase = g_y + (size_t)b * SS * DI + d0;

    int ch = w * 8 + chw;

    for (int t0 = 0; t0 < SS; t0 += 32) {
#pragma unroll
        for (int r = 0; r < 8; r++) {
            int cc = w * 8 + r;
            sh_d[cc][lane] = dbase[(size_t)cc * SS + t0 + lane];
            sh_u[cc][lane] = ubase[(size_t)cc * SS + t0 + lane];
        }
#pragma unroll
        for (int t = 0; t < 16; t++) {
            int idx = tid + t * 64;
            int i = idx >> 5, j = idx & 31;
            sh_bc[i][j] = pbase[(size_t)(t0 + i) * 96 + j];
        }
        __syncthreads();
#pragma unroll 4
        for (int i = 0; i < 32; i++) {
            float dlt = sh_d[ch][i];
            float uu  = sh_u[ch][i];
            float du  = dlt * uu;
            float4 b4 = *(const float4*)&sh_bc[i][q * 4];
            float4 c4 = *(const float4*)&sh_bc[i][16 + q * 4];
            float e0 = __expf(dlt * a0);
            float e1 = __expf(dlt * a1);
            float e2 = __expf(dlt * a2);
            float e3 = __expf(dlt * a3);
            s0 = e0 * s0 + du * b4.x;
            s1 = e1 * s1 + du * b4.y;
            s2 = e2 * s2 + du * b4.z;
            s3 = e3 * s3 + du * b4.w;
            float acc = s0 * c4.x + s1 * c4.y + s2 * c4.z + s3 * c4.w;
            acc += __shfl_xor_sync(0xffffffffu, acc, 1);
            acc += __shfl_xor_sync(0xffffffffu, acc, 2);
            if (q == 0)
                ybase[(size_t)(t0 + i) * DI + w * 8 + chw] = acc + uu * dpv;
        }
        __syncthreads();
    }
}

// ---------------- launch ----------------
extern "C" void kernel_launch(void* const* d_in, const int* in_sizes, int n_in,
                              void* d_out, int out_size)
{
    (void)in_sizes; (void)n_in; (void)out_size;
    const float* x     = (const float*)d_in[0];
    const float* Win   = (const float*)d_in[1];
    const float* Wconv = (const float*)d_in[2];
    const float* bconv = (const float*)d_in[3];
    const float* Wx    = (const float*)d_in[4];
    const float* Wdt   = (const float*)d_in[5];
    const float* bdt   = (const float*)d_in[6];
    const float* A_log = (const float*)d_in[7];
    const float* Dp    = (const float*)d_in[8];
    const float* Wout  = (const float*)d_in[9];
    float* out = (float*)d_out;

    cudaFuncSetAttribute(mma_gemm_kernel<1>, cudaFuncAttributeMaxDynamicSharedMemorySize, GSMEM_B);
    cudaFuncSetAttribute(mma_gemm_kernel<3>, cudaFuncAttributeMaxDynamicSharedMemorySize, GSMEM_B);

    split_x_kernel<<<4096, 256>>>(x);                                   // x -> A1 splits
    transpose_split_kernel<1><<<dim3(128, 32), dim3(32, 8)>>>(Win);     // Win^T splits
    mma_gemm_kernel<1><<<dim3(32, 32), 256, GSMEM_B>>>(nullptr);        // g_xz = x@Win
    conv_kernel<<<dim3(SS / 32, DI / 32, BB), 256>>>(Wconv, bconv);
    gemm_params_kernel<<<dim3(MM / 64), 256>>>(Wx);
    gemm_delta_kernel<<<dim3(MM / 32, DI / 64), 256>>>(Wdt, bdt);
    scan_kernel<<<dim3(BB * DI / 16), 64>>>(A_log, Dp);
    gate_split_kernel<<<8192, 256>>>();                                 // y*silu(z) -> A3 splits
    transpose_split_kernel<3><<<dim3(32, 64), dim3(32, 8)>>>(Wout);     // Wout^T splits
    mma_gemm_kernel<3><<<dim3(8, 32), 256, GSMEM_B>>>(out);             // out = A3@Wout
}

// round 4
// speedup vs baseline: 2.1525x; 1.1880x over previous
#include <cuda_runtime.h>
#include <cuda_fp16.h>
#include <math.h>
#include <stdint.h>

#define BB 2
#define SS 2048
#define DM 1024
#define DI 2048
#define DSTATE 16
#define RANK 64
#define MM (BB*SS)   /* 4096 rows (b,s) */

// ---------------- scratch (static device globals; no runtime allocation) ----------------
__device__ float g_xz[(size_t)MM * 2 * DI];     // [m][4096]  x@Win
__device__ float g_xbc[(size_t)MM * DI];        // conv+silu, [m][d]
__device__ float g_u[(size_t)BB * DI * SS];     // conv+silu, [b][d][s]
__device__ float g_params[(size_t)MM * 96];     // [m][96]  (delta_in | b | c)
__device__ float g_delta[(size_t)BB * DI * SS]; // softplus delta, [b][d][s]
__device__ float g_y[(size_t)MM * DI];          // scan output, [m][d]

// fp16 split operands for tensor-core GEMMs (A = Ah + Al, B = Bh only)
__device__ __half g_A1h[(size_t)MM * DM];
__device__ __half g_A1l[(size_t)MM * DM];
__device__ __half g_B1h[(size_t)(2*DI) * DM];   // Win^T [N=4096][K=1024]
__device__ __half g_A3h[(size_t)MM * DI];       // gated y [4096][2048]
__device__ __half g_A3l[(size_t)MM * DI];
__device__ __half g_B3h[(size_t)DM * DI];       // Wout^T [N=1024][K=2048]

// ================= low-level helpers (baseline PTX only: sm_80-class) =================
__device__ __forceinline__ uint32_t smem_to_u32(const void* smem_ptr) {
    uint32_t addr;
    asm("{ .reg .u64 tmp; cvta.to.shared.u64 tmp, %1; cvt.u32.u64 %0, tmp; }"
        : "=r"(addr) : "l"(smem_ptr));
    return addr;
}
#define CP_ASYNC16(saddr, gaddr) \
    asm volatile("cp.async.cg.shared.global [%0], [%1], 16;" :: "r"(saddr), "l"(gaddr))
#define CP_COMMIT() asm volatile("cp.async.commit_group;" ::: "memory")
#define CP_WAIT(n)  asm volatile("cp.async.wait_group %0;" :: "n"(n) : "memory")

__device__ __forceinline__ void ldsm4(uint32_t* r, uint32_t addr) {
    asm volatile("ldmatrix.sync.aligned.m8n8.x4.shared.b16 {%0,%1,%2,%3}, [%4];"
        : "=r"(r[0]), "=r"(r[1]), "=r"(r[2]), "=r"(r[3]) : "r"(addr));
}
__device__ __forceinline__ void mma16816(float* d, const uint32_t* a, const uint32_t* b) {
    asm volatile(
        "mma.sync.aligned.m16n8k16.row.col.f32.f16.f16.f32 "
        "{%0,%1,%2,%3}, {%4,%5,%6,%7}, {%8,%9}, {%0,%1,%2,%3};"
        : "+f"(d[0]), "+f"(d[1]), "+f"(d[2]), "+f"(d[3])
        : "r"(a[0]), "r"(a[1]), "r"(a[2]), "r"(a[3]), "r"(b[0]), "r"(b[1]));
}

// ================= split / transpose kernels =================
__device__ __forceinline__ void split1(float v, unsigned short& h, unsigned short& l) {
    __half hb = __float2half_rn(v);
    float r = v - __half2float(hb);
    __half lb = __float2half_rn(r);
    h = __half_as_ushort(hb);
    l = __half_as_ushort(lb);
}

__global__ void split_x_kernel(const float* __restrict__ src)   // -> g_A1h/l
{
    int i = blockIdx.x * 256 + threadIdx.x;   // 1M float4
    float4 v = ((const float4*)src)[i];
    unsigned short h0,h1,h2,h3,l0,l1,l2,l3;
    split1(v.x,h0,l0); split1(v.y,h1,l1); split1(v.z,h2,l2); split1(v.w,h3,l3);
    uint2 ph = make_uint2((uint32_t)h0 | ((uint32_t)h1<<16), (uint32_t)h2 | ((uint32_t)h3<<16));
    uint2 pl = make_uint2((uint32_t)l0 | ((uint32_t)l1<<16), (uint32_t)l2 | ((uint32_t)l3<<16));
    *(uint2*)&g_A1h[(size_t)i*4] = ph;
    *(uint2*)&g_A1l[(size_t)i*4] = pl;
}

__global__ void gate_split_kernel()   // A3 = g_y * silu(z) -> g_A3h/l
{
    int i = blockIdx.x * 256 + threadIdx.x;   // 2M float4
    int e = i * 4;
    int m = e >> 11;          // /2048
    int k = e & 2047;
    float4 y4 = *(const float4*)&g_y[(size_t)m * DI + k];
    float4 z4 = *(const float4*)&g_xz[(size_t)m * (2*DI) + DI + k];
    float a0 = y4.x * z4.x / (1.f + __expf(-z4.x));
    float a1 = y4.y * z4.y / (1.f + __expf(-z4.y));
    float a2 = y4.z * z4.z / (1.f + __expf(-z4.z));
    float a3 = y4.w * z4.w / (1.f + __expf(-z4.w));
    unsigned short h0,h1,h2,h3,l0,l1,l2,l3;
    split1(a0,h0,l0); split1(a1,h1,l1); split1(a2,h2,l2); split1(a3,h3,l3);
    uint2 ph = make_uint2((uint32_t)h0 | ((uint32_t)h1<<16), (uint32_t)h2 | ((uint32_t)h3<<16));
    uint2 pl = make_uint2((uint32_t)l0 | ((uint32_t)l1<<16), (uint32_t)l2 | ((uint32_t)l3<<16));
    *(uint2*)&g_A3h[(size_t)e] = ph;
    *(uint2*)&g_A3l[(size_t)e] = pl;
}

// WHICH=1: Win [1024][4096] -> g_B1h [4096][1024]
// WHICH=3: Wout [2048][1024] -> g_B3h [1024][2048]
template<int WHICH>
__global__ void transpose_split_kernel(const float* __restrict__ src)
{
    constexpr int KD = (WHICH == 1) ? DM : DI;       // dst inner dim (K)
    constexpr int ND = (WHICH == 1) ? 2*DI : DM;     // dst outer dim (N)
    __half* dh = (WHICH == 1) ? g_B1h : g_B3h;
    __shared__ float t[32][33];
    int n0 = blockIdx.x * 32, k0 = blockIdx.y * 32;
    int tx = threadIdx.x, ty = threadIdx.y;
#pragma unroll
    for (int i = 0; i < 4; i++)
        t[ty + i*8][tx] = src[(size_t)(k0 + ty + i*8) * ND + n0 + tx];
    __syncthreads();
#pragma unroll
    for (int i = 0; i < 4; i++) {
        int n = n0 + ty + i*8, k = k0 + tx;
        dh[(size_t)n * KD + k] = __float2half_rn(t[tx][ty + i*8]);
    }
}

// ================= mma.sync GEMM: C[4096][N] = A @ B^T (fp16 2-term split) =================
// Block tile 128x128, 8 warps (warp tile 32m x 64n), K-chunk 32, 3-stage cp.async.
static constexpr int TSTRIDE = 40;                        // padded row stride (fp16 elems)
static constexpr uint32_t TILE_B = 128 * TSTRIDE * 2;     // 10240 B per tile
static constexpr uint32_t STAGE_B = 3 * TILE_B;           // Ah Al Bh
static constexpr uint32_t GSMEM_B = 3 * STAGE_B;          // 92160 B (3 stages)

__device__ __forceinline__ void load_tile_ca(uint32_t sbase, const __half* g,
                                             int row0, int ktot, int kbase, int tid)
{
#pragma unroll
    for (int it = 0; it < 2; it++) {
        int u = tid + it * 256;            // 0..511
        int r = u >> 2, seg = u & 3;
        uint32_t s = sbase + (uint32_t)(r * TSTRIDE + seg * 8) * 2;
        const __half* gp = g + (size_t)(row0 + r) * ktot + kbase + seg * 8;
        CP_ASYNC16(s, gp);
    }
}

template<int WHICH>
__global__ __launch_bounds__(256, 1)
void mma_gemm_kernel(float* __restrict__ Cout)
{
    constexpr int KTOT = (WHICH == 1) ? DM : DI;
    constexpr int NC = KTOT / 32;
    constexpr int LDC = (WHICH == 1) ? (2*DI) : DM;
    const __half* Ah = (WHICH == 1) ? g_A1h : g_A3h;
    const __half* Al = (WHICH == 1) ? g_A1l : g_A3l;
    const __half* Bh = (WHICH == 1) ? g_B1h : g_B3h;

    extern __shared__ __align__(16) char smem[];
    uint32_t sb = smem_to_u32(smem);

    int tid = threadIdx.x;
    int lane = tid & 31, wid = tid >> 5;
    int wm = wid & 3;          // 0..3 -> 32-row slice
    int wn = wid >> 2;         // 0..1 -> 64-col slice
    int m0 = blockIdx.y * 128;
    int n0 = blockIdx.x * 128;

    float d[2][8][4];
#pragma unroll
    for (int mt = 0; mt < 2; mt++)
#pragma unroll
        for (int nt = 0; nt < 8; nt++)
#pragma unroll
            for (int i = 0; i < 4; i++) d[mt][nt][i] = 0.f;

    const uint32_t OA_H = 0, OA_L = TILE_B, OB_H = 2*TILE_B;

    // prologue: stages 0 and 1
#pragma unroll
    for (int p = 0; p < 2; p++) {
        uint32_t base = sb + p * STAGE_B;
        int kb = p * 32;
        load_tile_ca(base + OA_H, Ah, m0, KTOT, kb, tid);
        load_tile_ca(base + OA_L, Al, m0, KTOT, kb, tid);
        load_tile_ca(base + OB_H, Bh, n0, KTOT, kb, tid);
        CP_COMMIT();
    }

    int quad = lane >> 3, lrow = lane & 7;
    int st = 0;

    for (int kc = 0; kc < NC; kc++) {
        if (kc + 1 < NC) CP_WAIT(1); else CP_WAIT(0);
        __syncthreads();

        // prefetch stage kc+2 (its buffer was consumed in iteration kc-1)
        if (kc + 2 < NC) {
            int pst = st + 2; if (pst >= 3) pst -= 3;
            uint32_t base = sb + pst * STAGE_B;
            int kb = (kc + 2) * 32;
            load_tile_ca(base + OA_H, Ah, m0, KTOT, kb, tid);
            load_tile_ca(base + OA_L, Al, m0, KTOT, kb, tid);
            load_tile_ca(base + OB_H, Bh, n0, KTOT, kb, tid);
            CP_COMMIT();
        }

        uint32_t base = sb + st * STAGE_B;
#pragma unroll
        for (int ks = 0; ks < 2; ks++) {
            int k16 = ks * 16;
            uint32_t aH[2][4], aL[2][4];
#pragma unroll
            for (int mt = 0; mt < 2; mt++) {
                int row = wm * 32 + mt * 16 + (quad & 1) * 8 + lrow;
                uint32_t off = (uint32_t)(row * TSTRIDE + k16 + (quad >> 1) * 8) * 2;
                ldsm4(aH[mt], base + OA_H + off);
                ldsm4(aL[mt], base + OA_L + off);
            }
            uint32_t bH[8][2];
#pragma unroll
            for (int np = 0; np < 4; np++) {
                int nrow = wn * 64 + np * 16 + (quad >> 1) * 8 + lrow;
                uint32_t off = (uint32_t)(nrow * TSTRIDE + k16 + (quad & 1) * 8) * 2;
                uint32_t t[4];
                ldsm4(t, base + OB_H + off);
                bH[np*2][0] = t[0]; bH[np*2][1] = t[1];
                bH[np*2+1][0] = t[2]; bH[np*2+1][1] = t[3];
            }
#pragma unroll
            for (int mt = 0; mt < 2; mt++)
#pragma unroll
                for (int nt = 0; nt < 8; nt++) {
                    mma16816(d[mt][nt], aH[mt], bH[nt]);
                    mma16816(d[mt][nt], aL[mt], bH[nt]);
                }
        }
        __syncthreads();
        st++; if (st >= 3) st -= 3;
    }

    float* C = (WHICH == 1) ? g_xz : Cout;
#pragma unroll
    for (int mt = 0; mt < 2; mt++)
#pragma unroll
        for (int nt = 0; nt < 8; nt++) {
            int row = m0 + wm * 32 + mt * 16 + (lane >> 2);
            int col = n0 + wn * 64 + nt * 8 + (lane & 3) * 2;
            float2 v0 = {d[mt][nt][0], d[mt][nt][1]};
            float2 v1 = {d[mt][nt][2], d[mt][nt][3]};
            *(float2*)&C[(size_t)row * LDC + col] = v0;
            *(float2*)&C[(size_t)(row + 8) * LDC + col] = v1;
        }
}

// ---------------- conv: depthwise causal K=4 + bias + silu ----------------
__global__ __launch_bounds__(256)
void conv_kernel(const float* __restrict__ Wconv, const float* __restrict__ bconv)
{
    __shared__ float sh_x[35][33];
    __shared__ float sh_o[32][33];
    __shared__ float sh_w[4][32];
    __shared__ float sh_b[32];
    int tid = threadIdx.x;
    int b  = blockIdx.z;
    int d0 = blockIdx.y * 32;
    int s0 = blockIdx.x * 32;

    for (int idx = tid; idx < 35 * 32; idx += 256) {
        int r = idx >> 5, c = idx & 31;
        int s = s0 - 3 + r;
        float v = 0.f;
        if (s >= 0)
            v = g_xz[((size_t)(b * SS + s)) * (2 * DI) + d0 + c];
        sh_x[r][c] = v;
    }
    if (tid < 128) {
        int k = tid >> 5, c = tid & 31;
        sh_w[k][c] = Wconv[(size_t)(d0 + c) * 4 + k];
    }
    if (tid < 32) sh_b[tid] = bconv[d0 + tid];
    __syncthreads();

    int td = tid & 31, tg = tid >> 5;
#pragma unroll
    for (int si = 0; si < 4; si++) {
        int ss = tg + si * 8;
        float o = sh_b[td]
                + sh_x[ss + 0][td] * sh_w[0][td]
                + sh_x[ss + 1][td] * sh_w[1][td]
                + sh_x[ss + 2][td] * sh_w[2][td]
                + sh_x[ss + 3][td] * sh_w[3][td];
        o = o / (1.f + __expf(-o));
        sh_o[ss][td] = o;
        g_xbc[((size_t)(b * SS + s0 + ss)) * DI + d0 + td] = o;
    }
    __syncthreads();
#pragma unroll
    for (int di = 0; di < 4; di++) {
        int dd = tg + di * 8;
        g_u[((size_t)(b * DI + d0 + dd)) * SS + s0 + td] = sh_o[td][dd];
    }
}

// ---------------- GEMM2: g_params = g_xbc @ Wx ----------------
__global__ __launch_bounds__(256)
void gemm_params_kernel(const float* __restrict__ Wx)
{
    __shared__ float shA[16][68];
    __shared__ float shB[16][96];
    int tid = threadIdx.x;
    int m0 = blockIdx.x * 64;
    int tx = tid & 15, ty = tid >> 4;

    float acc[4][6];
#pragma unroll
    for (int i = 0; i < 4; i++)
#pragma unroll
        for (int j = 0; j < 6; j++) acc[i][j] = 0.f;

    int ar = tid >> 2;
    int ac = (tid & 3) * 4;

    for (int k0 = 0; k0 < DI; k0 += 16) {
        float4 a4 = *(const float4*)&g_xbc[(size_t)(m0 + ar) * DI + k0 + ac];
        shA[ac + 0][ar] = a4.x;
        shA[ac + 1][ar] = a4.y;
        shA[ac + 2][ar] = a4.z;
        shA[ac + 3][ar] = a4.w;
#pragma unroll
        for (int t = 0; t < 6; t++) {
            int idx = tid + t * 256;
            int r = idx / 96, c = idx % 96;
            shB[r][c] = Wx[(size_t)(k0 + r) * 96 + c];
        }
        __syncthreads();
#pragma unroll
        for (int kk = 0; kk < 16; kk++) {
            float ra[4], rb[6];
#pragma unroll
            for (int i = 0; i < 4; i++) ra[i] = shA[kk][ty * 4 + i];
#pragma unroll
            for (int j = 0; j < 6; j++) rb[j] = shB[kk][tx * 6 + j];
#pragma unroll
            for (int i = 0; i < 4; i++)
#pragma unroll
                for (int j = 0; j < 6; j++)
                    acc[i][j] += ra[i] * rb[j];
        }
        __syncthreads();
    }
#pragma unroll
    for (int i = 0; i < 4; i++)
#pragma unroll
        for (int j = 0; j < 6; j++)
            g_params[(size_t)(m0 + ty * 4 + i) * 96 + tx * 6 + j] = acc[i][j];
}

// ---------------- delta GEMM: softplus(delta_in @ Wdt + bdt) ----------------
__global__ __launch_bounds__(256)
void gemm_delta_kernel(const float* __restrict__ Wdt, const float* __restrict__ bdt)
{
    __shared__ float shA[32][65];
    __shared__ float shB[64][64];
    int tid = threadIdx.x;
    int m0 = blockIdx.x * 32;
    int dn0 = blockIdx.y * 64;

#pragma unroll
    for (int t = 0; t < 8; t++) {
        int idx = tid + t * 256;
        int r = idx >> 6, c = idx & 63;
        shA[r][c] = g_params[(size_t)(m0 + r) * 96 + c];
    }
#pragma unroll
    for (int t = 0; t < 16; t++) {
        int idx = tid + t * 256;
        int r = idx >> 6, c = idx & 63;
        shB[r][c] = Wdt[(size_t)r * DI + dn0 + c];
    }
    __syncthreads();

    int s_loc = tid & 31;
    int dgrp = tid >> 5;
    float acc[8];
#pragma unroll
    for (int j = 0; j < 8; j++) acc[j] = 0.f;

#pragma unroll 8
    for (int k = 0; k < 64; k++) {
        float av = shA[s_loc][k];
        float4 b0 = *(const float4*)&shB[k][dgrp * 8];
        float4 b1 = *(const float4*)&shB[k][dgrp * 8 + 4];
        acc[0] += av * b0.x; acc[1] += av * b0.y;
        acc[2] += av * b0.z; acc[3] += av * b0.w;
        acc[4] += av * b1.x; acc[5] += av * b1.y;
        acc[6] += av * b1.z; acc[7] += av * b1.w;
    }

    int m = m0 + s_loc;
    int b = m >> 11;
    int s = m & 2047;
#pragma unroll
    for (int j = 0; j < 8; j++) {
        int d = dn0 + dgrp * 8 + j;
        float t = acc[j] + bdt[d];
        float sp = fmaxf(t, 0.f) + log1pf(__expf(-fabsf(t)));
        g_delta[((size_t)(b * DI + d)) * SS + s] = sp;
    }
}

// ---------------- selective scan ----------------
__global__ __launch_bounds__(64, 8)
void scan_kernel(const float* __restrict__ A_log, const float* __restrict__ Dp)
{
    __shared__ float sh_d[16][33];
    __shared__ float sh_u[16][33];
    __shared__ float sh_bc[32][32];
    int tid = threadIdx.x;
    int lane = tid & 31, w = tid >> 5;
    int gch0 = blockIdx.x * 16;
    int b  = gch0 / DI;
    int d0 = gch0 % DI;
    int chw = lane >> 2;
    int q = lane & 3;
    int d = d0 + w * 8 + chw;

    float a0, a1, a2, a3;
    {
        float4 al = *(const float4*)&A_log[(size_t)d * DSTATE + q * 4];
        a0 = -__expf(al.x); a1 = -__expf(al.y);
        a2 = -__expf(al.z); a3 = -__expf(al.w);
    }
    float dpv = Dp[d];
    float s0 = 0.f, s1 = 0.f, s2 = 0.f, s3 = 0.f;

    const float* dbase = g_delta + (size_t)(b * DI + d0) * SS;
    const float* ubase = g_u     + (size_t)(b * DI + d0) * SS;
    const float* pbase = g_params + (size_t)b * SS * 96 + 64;
    float* ybase = g_y + (size_t)b * SS * DI + d0;

    int ch = w * 8 + chw;

    for (int t0 = 0; t0 < SS; t0 += 32) {
#pragma unroll
        for (int r = 0; r < 8; r++) {
            int cc = w * 8 + r;
            sh_d[cc][lane] = dbase[(size_t)cc * SS + t0 + lane];
            sh_u[cc][lane] = ubase[(size_t)cc * SS + t0 + lane];
        }
#pragma unroll
        for (int t = 0; t < 16; t++) {
            int idx = tid + t * 64;
            int i = idx >> 5, j = idx & 31;
            sh_bc[i][j] = pbase[(size_t)(t0 + i) * 96 + j];
        }
        __syncthreads();
#pragma unroll 4
        for (int i = 0; i < 32; i++) {
            float dlt = sh_d[ch][i];
            float uu  = sh_u[ch][i];
            float du  = dlt * uu;
            float4 b4 = *(const float4*)&sh_bc[i][q * 4];
            float4 c4 = *(const float4*)&sh_bc[i][16 + q * 4];
            float e0 = __expf(dlt * a0);
            float e1 = __expf(dlt * a1);
            float e2 = __expf(dlt * a2);
            float e3 = __expf(dlt * a3);
            s0 = e0 * s0 + du * b4.x;
            s1 = e1 * s1 + du * b4.y;
            s2 = e2 * s2 + du * b4.z;
            s3 = e3 * s3 + du * b4.w;
            float acc = s0 * c4.x + s1 * c4.y + s2 * c4.z + s3 * c4.w;
            acc += __shfl_xor_sync(0xffffffffu, acc, 1);
            acc += __shfl_xor_sync(0xffffffffu, acc, 2);
            if (q == 0)
                ybase[(size_t)(t0 + i) * DI + w * 8 + chw] = acc + uu * dpv;
        }
        __syncthreads();
    }
}

// ---------------- launch ----------------
extern "C" void kernel_launch(void* const* d_in, const int* in_sizes, int n_in,
                              void* d_out, int out_size)
{
    (void)in_sizes; (void)n_in; (void)out_size;
    const float* x     = (const float*)d_in[0];
    const float* Win   = (const float*)d_in[1];
    const float* Wconv = (const float*)d_in[2];
    const float* bconv = (const float*)d_in[3];
    const float* Wx    = (const float*)d_in[4];
    const float* Wdt   = (const float*)d_in[5];
    const float* bdt   = (const float*)d_in[6];
    const float* A_log = (const float*)d_in[7];
    const float* Dp    = (const float*)d_in[8];
    const float* Wout  = (const float*)d_in[9];
    float* out = (float*)d_out;

    cudaFuncSetAttribute(mma_gemm_kernel<1>, cudaFuncAttributeMaxDynamicSharedMemorySize, GSMEM_B);
    cudaFuncSetAttribute(mma_gemm_kernel<3>, cudaFuncAttributeMaxDynamicSharedMemorySize, GSMEM_B);

    split_x_kernel<<<4096, 256>>>(x);                                   // x -> A1 splits
    transpose_split_kernel<1><<<dim3(128, 32), dim3(32, 8)>>>(Win);     // Win^T fp16
    mma_gemm_kernel<1><<<dim3(32, 32), 256, GSMEM_B>>>(nullptr);        // g_xz = x@Win
    conv_kernel<<<dim3(SS / 32, DI / 32, BB), 256>>>(Wconv, bconv);
    gemm_params_kernel<<<dim3(MM / 64), 256>>>(Wx);
    gemm_delta_kernel<<<dim3(MM / 32, DI / 64), 256>>>(Wdt, bdt);
    scan_kernel<<<dim3(BB * DI / 16), 64>>>(A_log, Dp);
    gate_split_kernel<<<8192, 256>>>();                                 // y*silu(z) -> A3 splits
    transpose_split_kernel<3><<<dim3(32, 64), dim3(32, 8)>>>(Wout);     // Wout^T fp16
    mma_gemm_kernel<3><<<dim3(8, 32), 256, GSMEM_B>>>(out);             // out = A3@Wout
}

// round 5
// speedup vs baseline: 2.8562x; 1.3269x over previous
#include <cuda_runtime.h>
#include <cuda_fp16.h>
#include <math.h>
#include <stdint.h>

#define BB 2
#define SS 2048
#define DM 1024
#define DI 2048
#define DSTATE 16
#define RANK 64
#define MM (BB*SS)   /* 4096 rows (b,s) */

// ---------------- scratch (static device globals; no runtime allocation) ----------------
__device__ float g_xz[(size_t)MM * 2 * DI];     // [m][4096]  x@Win
__device__ float g_xbc[(size_t)MM * DI];        // conv+silu, [m][d]
__device__ float g_u[(size_t)BB * DI * SS];     // conv+silu, [b][d][s]
__device__ float g_params[(size_t)MM * 96];     // [m][96]  (delta_in | b | c)
__device__ float g_delta[(size_t)BB * DI * SS]; // softplus delta, [b][d][s]
__device__ float g_y[(size_t)MM * DI];          // scan output, [m][d]

// fp16 operands for tensor-core GEMMs
__device__ __half g_A1h[(size_t)MM * DM];
__device__ __half g_B1h[(size_t)(2*DI) * DM];   // Win^T [N=4096][K=1024]
__device__ __half g_A3h[(size_t)MM * DI];       // gated y [4096][2048]
__device__ __half g_B3h[(size_t)DM * DI];       // Wout^T [N=1024][K=2048]

// ================= low-level helpers (baseline PTX only: sm_80-class) =================
__device__ __forceinline__ uint32_t smem_to_u32(const void* smem_ptr) {
    uint32_t addr;
    asm("{ .reg .u64 tmp; cvta.to.shared.u64 tmp, %1; cvt.u32.u64 %0, tmp; }"
        : "=r"(addr) : "l"(smem_ptr));
    return addr;
}
#define CP_ASYNC16(saddr, gaddr) \
    asm volatile("cp.async.cg.shared.global [%0], [%1], 16;" :: "r"(saddr), "l"(gaddr))
#define CP_COMMIT() asm volatile("cp.async.commit_group;" ::: "memory")
#define CP_WAIT(n)  asm volatile("cp.async.wait_group %0;" :: "n"(n) : "memory")

__device__ __forceinline__ void ldsm4(uint32_t* r, uint32_t addr) {
    asm volatile("ldmatrix.sync.aligned.m8n8.x4.shared.b16 {%0,%1,%2,%3}, [%4];"
        : "=r"(r[0]), "=r"(r[1]), "=r"(r[2]), "=r"(r[3]) : "r"(addr));
}
__device__ __forceinline__ void mma16816(float* d, const uint32_t* a, const uint32_t* b) {
    asm volatile(
        "mma.sync.aligned.m16n8k16.row.col.f32.f16.f16.f32 "
        "{%0,%1,%2,%3}, {%4,%5,%6,%7}, {%8,%9}, {%0,%1,%2,%3};"
        : "+f"(d[0]), "+f"(d[1]), "+f"(d[2]), "+f"(d[3])
        : "r"(a[0]), "r"(a[1]), "r"(a[2]), "r"(a[3]), "r"(b[0]), "r"(b[1]));
}

// ================= convert / transpose kernels =================
__global__ void convert_x_kernel(const float* __restrict__ src)   // -> g_A1h
{
    int i = blockIdx.x * 256 + threadIdx.x;   // 1M float4
    float4 v = ((const float4*)src)[i];
    __half2 p0 = __floats2half2_rn(v.x, v.y);
    __half2 p1 = __floats2half2_rn(v.z, v.w);
    uint2 ph = make_uint2(*(uint32_t*)&p0, *(uint32_t*)&p1);
    *(uint2*)&g_A1h[(size_t)i*4] = ph;
}

__global__ void gate_convert_kernel()   // A3 = g_y * silu(z) -> g_A3h
{
    int i = blockIdx.x * 256 + threadIdx.x;   // 2M float4
    int e = i * 4;
    int m = e >> 11;          // /2048
    int k = e & 2047;
    float4 y4 = *(const float4*)&g_y[(size_t)m * DI + k];
    float4 z4 = *(const float4*)&g_xz[(size_t)m * (2*DI) + DI + k];
    float a0 = y4.x * z4.x / (1.f + __expf(-z4.x));
    float a1 = y4.y * z4.y / (1.f + __expf(-z4.y));
    float a2 = y4.z * z4.z / (1.f + __expf(-z4.z));
    float a3 = y4.w * z4.w / (1.f + __expf(-z4.w));
    __half2 p0 = __floats2half2_rn(a0, a1);
    __half2 p1 = __floats2half2_rn(a2, a3);
    uint2 ph = make_uint2(*(uint32_t*)&p0, *(uint32_t*)&p1);
    *(uint2*)&g_A3h[(size_t)e] = ph;
}

// WHICH=1: Win [1024][4096] -> g_B1h [4096][1024]
// WHICH=3: Wout [2048][1024] -> g_B3h [1024][2048]
template<int WHICH>
__global__ void transpose_convert_kernel(const float* __restrict__ src)
{
    constexpr int KD = (WHICH == 1) ? DM : DI;       // dst inner dim (K)
    constexpr int ND = (WHICH == 1) ? 2*DI : DM;     // dst outer dim (N)
    __half* dh = (WHICH == 1) ? g_B1h : g_B3h;
    __shared__ float t[32][33];
    int n0 = blockIdx.x * 32, k0 = blockIdx.y * 32;
    int tx = threadIdx.x, ty = threadIdx.y;
#pragma unroll
    for (int i = 0; i < 4; i++)
        t[ty + i*8][tx] = src[(size_t)(k0 + ty + i*8) * ND + n0 + tx];
    __syncthreads();
#pragma unroll
    for (int i = 0; i < 4; i++) {
        int n = n0 + ty + i*8, k = k0 + tx;
        dh[(size_t)n * KD + k] = __float2half_rn(t[tx][ty + i*8]);
    }
}

// ================= mma.sync GEMM: C[4096][N] = A @ B^T (fp16) =================
// Block tile 128x128, 8 warps (warp tile 32m x 64n), K-chunk 32, 3-stage cp.async,
// 2 CTAs/SM.
static constexpr int TSTRIDE = 40;                        // padded row stride (fp16 elems)
static constexpr uint32_t TILE_B = 128 * TSTRIDE * 2;     // 10240 B per tile
static constexpr uint32_t STAGE_B = 2 * TILE_B;           // A, B
static constexpr uint32_t GSMEM_B = 3 * STAGE_B;          // 61440 B (3 stages)

__device__ __forceinline__ void load_tile_ca(uint32_t sbase, const __half* g,
                                             int row0, int ktot, int kbase, int tid)
{
#pragma unroll
    for (int it = 0; it < 2; it++) {
        int u = tid + it * 256;            // 0..511
        int r = u >> 2, seg = u & 3;
        uint32_t s = sbase + (uint32_t)(r * TSTRIDE + seg * 8) * 2;
        const __half* gp = g + (size_t)(row0 + r) * ktot + kbase + seg * 8;
        CP_ASYNC16(s, gp);
    }
}

template<int WHICH>
__global__ __launch_bounds__(256, 2)
void mma_gemm_kernel(float* __restrict__ Cout)
{
    constexpr int KTOT = (WHICH == 1) ? DM : DI;
    constexpr int NC = KTOT / 32;
    constexpr int LDC = (WHICH == 1) ? (2*DI) : DM;
    const __half* Ah = (WHICH == 1) ? g_A1h : g_A3h;
    const __half* Bh = (WHICH == 1) ? g_B1h : g_B3h;

    extern __shared__ __align__(16) char smem[];
    uint32_t sb = smem_to_u32(smem);

    int tid = threadIdx.x;
    int lane = tid & 31, wid = tid >> 5;
    int wm = wid & 3;          // 0..3 -> 32-row slice
    int wn = wid >> 2;         // 0..1 -> 64-col slice
    int m0 = blockIdx.y * 128;
    int n0 = blockIdx.x * 128;

    float d[2][8][4];
#pragma unroll
    for (int mt = 0; mt < 2; mt++)
#pragma unroll
        for (int nt = 0; nt < 8; nt++)
#pragma unroll
            for (int i = 0; i < 4; i++) d[mt][nt][i] = 0.f;

    const uint32_t OA = 0, OB = TILE_B;

    // prologue: stages 0 and 1
#pragma unroll
    for (int p = 0; p < 2; p++) {
        uint32_t base = sb + p * STAGE_B;
        int kb = p * 32;
        load_tile_ca(base + OA, Ah, m0, KTOT, kb, tid);
        load_tile_ca(base + OB, Bh, n0, KTOT, kb, tid);
        CP_COMMIT();
    }

    int quad = lane >> 3, lrow = lane & 7;
    int st = 0;

    for (int kc = 0; kc < NC; kc++) {
        if (kc + 1 < NC) CP_WAIT(1); else CP_WAIT(0);
        __syncthreads();

        // prefetch stage kc+2
        if (kc + 2 < NC) {
            int pst = st + 2; if (pst >= 3) pst -= 3;
            uint32_t base = sb + pst * STAGE_B;
            int kb = (kc + 2) * 32;
            load_tile_ca(base + OA, Ah, m0, KTOT, kb, tid);
            load_tile_ca(base + OB, Bh, n0, KTOT, kb, tid);
            CP_COMMIT();
        }

        uint32_t base = sb + st * STAGE_B;
#pragma unroll
        for (int ks = 0; ks < 2; ks++) {
            int k16 = ks * 16;
            uint32_t aH[2][4];
#pragma unroll
            for (int mt = 0; mt < 2; mt++) {
                int row = wm * 32 + mt * 16 + (quad & 1) * 8 + lrow;
                uint32_t off = (uint32_t)(row * TSTRIDE + k16 + (quad >> 1) * 8) * 2;
                ldsm4(aH[mt], base + OA + off);
            }
            uint32_t bH[8][2];
#pragma unroll
            for (int np = 0; np < 4; np++) {
                int nrow = wn * 64 + np * 16 + (quad >> 1) * 8 + lrow;
                uint32_t off = (uint32_t)(nrow * TSTRIDE + k16 + (quad & 1) * 8) * 2;
                uint32_t t[4];
                ldsm4(t, base + OB + off);
                bH[np*2][0] = t[0]; bH[np*2][1] = t[1];
                bH[np*2+1][0] = t[2]; bH[np*2+1][1] = t[3];
            }
#pragma unroll
            for (int mt = 0; mt < 2; mt++)
#pragma unroll
                for (int nt = 0; nt < 8; nt++)
                    mma16816(d[mt][nt], aH[mt], bH[nt]);
        }
        __syncthreads();
        st++; if (st >= 3) st -= 3;
    }

    float* C = (WHICH == 1) ? g_xz : Cout;
#pragma unroll
    for (int mt = 0; mt < 2; mt++)
#pragma unroll
        for (int nt = 0; nt < 8; nt++) {
            int row = m0 + wm * 32 + mt * 16 + (lane >> 2);
            int col = n0 + wn * 64 + nt * 8 + (lane & 3) * 2;
            float2 v0 = {d[mt][nt][0], d[mt][nt][1]};
            float2 v1 = {d[mt][nt][2], d[mt][nt][3]};
            *(float2*)&C[(size_t)row * LDC + col] = v0;
            *(float2*)&C[(size_t)(row + 8) * LDC + col] = v1;
        }
}

// ---------------- conv: depthwise causal K=4 + bias + silu ----------------
__global__ __launch_bounds__(256)
void conv_kernel(const float* __restrict__ Wconv, const float* __restrict__ bconv)
{
    __shared__ float sh_x[35][33];
    __shared__ float sh_o[32][33];
    __shared__ float sh_w[4][32];
    __shared__ float sh_b[32];
    int tid = threadIdx.x;
    int b  = blockIdx.z;
    int d0 = blockIdx.y * 32;
    int s0 = blockIdx.x * 32;

    for (int idx = tid; idx < 35 * 32; idx += 256) {
        int r = idx >> 5, c = idx & 31;
        int s = s0 - 3 + r;
        float v = 0.f;
        if (s >= 0)
            v = g_xz[((size_t)(b * SS + s)) * (2 * DI) + d0 + c];
        sh_x[r][c] = v;
    }
    if (tid < 128) {
        int k = tid >> 5, c = tid & 31;
        sh_w[k][c] = Wconv[(size_t)(d0 + c) * 4 + k];
    }
    if (tid < 32) sh_b[tid] = bconv[d0 + tid];
    __syncthreads();

    int td = tid & 31, tg = tid >> 5;
#pragma unroll
    for (int si = 0; si < 4; si++) {
        int ss = tg + si * 8;
        float o = sh_b[td]
                + sh_x[ss + 0][td] * sh_w[0][td]
                + sh_x[ss + 1][td] * sh_w[1][td]
                + sh_x[ss + 2][td] * sh_w[2][td]
                + sh_x[ss + 3][td] * sh_w[3][td];
        o = o / (1.f + __expf(-o));
        sh_o[ss][td] = o;
        g_xbc[((size_t)(b * SS + s0 + ss)) * DI + d0 + td] = o;
    }
    __syncthreads();
#pragma unroll
    for (int di = 0; di < 4; di++) {
        int dd = tg + di * 8;
        g_u[((size_t)(b * DI + d0 + dd)) * SS + s0 + td] = sh_o[td][dd];
    }
}

// ---------------- GEMM2: g_params = g_xbc @ Wx ----------------
__global__ __launch_bounds__(256)
void gemm_params_kernel(const float* __restrict__ Wx)
{
    __shared__ float shA[16][68];
    __shared__ float shB[16][96];
    int tid = threadIdx.x;
    int m0 = blockIdx.x * 64;
    int tx = tid & 15, ty = tid >> 4;

    float acc[4][6];
#pragma unroll
    for (int i = 0; i < 4; i++)
#pragma unroll
        for (int j = 0; j < 6; j++) acc[i][j] = 0.f;

    int ar = tid >> 2;
    int ac = (tid & 3) * 4;

    for (int k0 = 0; k0 < DI; k0 += 16) {
        float4 a4 = *(const float4*)&g_xbc[(size_t)(m0 + ar) * DI + k0 + ac];
        shA[ac + 0][ar] = a4.x;
        shA[ac + 1][ar] = a4.y;
        shA[ac + 2][ar] = a4.z;
        shA[ac + 3][ar] = a4.w;
#pragma unroll
        for (int t = 0; t < 6; t++) {
            int idx = tid + t * 256;
            int r = idx / 96, c = idx % 96;
            shB[r][c] = Wx[(size_t)(k0 + r) * 96 + c];
        }
        __syncthreads();
#pragma unroll
        for (int kk = 0; kk < 16; kk++) {
            float ra[4], rb[6];
#pragma unroll
            for (int i = 0; i < 4; i++) ra[i] = shA[kk][ty * 4 + i];
#pragma unroll
            for (int j = 0; j < 6; j++) rb[j] = shB[kk][tx * 6 + j];
#pragma unroll
            for (int i = 0; i < 4; i++)
#pragma unroll
                for (int j = 0; j < 6; j++)
                    acc[i][j] += ra[i] * rb[j];
        }
        __syncthreads();
    }
#pragma unroll
    for (int i = 0; i < 4; i++)
#pragma unroll
        for (int j = 0; j < 6; j++)
            g_params[(size_t)(m0 + ty * 4 + i) * 96 + tx * 6 + j] = acc[i][j];
}

// ---------------- delta GEMM: softplus(delta_in @ Wdt + bdt) ----------------
__global__ __launch_bounds__(256)
void gemm_delta_kernel(const float* __restrict__ Wdt, const float* __restrict__ bdt)
{
    __shared__ float shA[32][65];
    __shared__ float shB[64][64];
    int tid = threadIdx.x;
    int m0 = blockIdx.x * 32;
    int dn0 = blockIdx.y * 64;

#pragma unroll
    for (int t = 0; t < 8; t++) {
        int idx = tid + t * 256;
        int r = idx >> 6, c = idx & 63;
        shA[r][c] = g_params[(size_t)(m0 + r) * 96 + c];
    }
#pragma unroll
    for (int t = 0; t < 16; t++) {
        int idx = tid + t * 256;
        int r = idx >> 6, c = idx & 63;
        shB[r][c] = Wdt[(size_t)r * DI + dn0 + c];
    }
    __syncthreads();

    int s_loc = tid & 31;
    int dgrp = tid >> 5;
    float acc[8];
#pragma unroll
    for (int j = 0; j < 8; j++) acc[j] = 0.f;

#pragma unroll 8
    for (int k = 0; k < 64; k++) {
        float av = shA[s_loc][k];
        float4 b0 = *(const float4*)&shB[k][dgrp * 8];
        float4 b1 = *(const float4*)&shB[k][dgrp * 8 + 4];
        acc[0] += av * b0.x; acc[1] += av * b0.y;
        acc[2] += av * b0.z; acc[3] += av * b0.w;
        acc[4] += av * b1.x; acc[5] += av * b1.y;
        acc[6] += av * b1.z; acc[7] += av * b1.w;
    }

    int m = m0 + s_loc;
    int b = m >> 11;
    int s = m & 2047;
#pragma unroll
    for (int j = 0; j < 8; j++) {
        int d = dn0 + dgrp * 8 + j;
        float t = acc[j] + bdt[d];
        float sp = fmaxf(t, 0.f) + log1pf(__expf(-fabsf(t)));
        g_delta[((size_t)(b * DI + d)) * SS + s] = sp;
    }
}

// ---------------- selective scan ----------------
__global__ __launch_bounds__(64, 8)
void scan_kernel(const float* __restrict__ A_log, const float* __restrict__ Dp)
{
    __shared__ float sh_d[16][33];
    __shared__ float sh_u[16][33];
    __shared__ float sh_bc[32][32];
    int tid = threadIdx.x;
    int lane = tid & 31, w = tid >> 5;
    int gch0 = blockIdx.x * 16;
    int b  = gch0 / DI;
    int d0 = gch0 % DI;
    int chw = lane >> 2;
    int q = lane & 3;
    int d = d0 + w * 8 + chw;

    float a0, a1, a2, a3;
    {
        float4 al = *(const float4*)&A_log[(size_t)d * DSTATE + q * 4];
        a0 = -__expf(al.x); a1 = -__expf(al.y);
        a2 = -__expf(al.z); a3 = -__expf(al.w);
    }
    float dpv = Dp[d];
    float s0 = 0.f, s1 = 0.f, s2 = 0.f, s3 = 0.f;

    const float* dbase = g_delta + (size_t)(b * DI + d0) * SS;
    const float* ubase = g_u     + (size_t)(b * DI + d0) * SS;
    const float* pbase = g_params + (size_t)b * SS * 96 + 64;
    float* ybase = g_y + (size_t)b * SS * DI + d0;

    int ch = w * 8 + chw;

    for (int t0 = 0; t0 < SS; t0 += 32) {
#pragma unroll
        for (int r = 0; r < 8; r++) {
            int cc = w * 8 + r;
            sh_d[cc][lane] = dbase[(size_t)cc * SS + t0 + lane];
            sh_u[cc][lane] = ubase[(size_t)cc * SS + t0 + lane];
        }
#pragma unroll
        for (int t = 0; t < 16; t++) {
            int idx = tid + t * 64;
            int i = idx >> 5, j = idx & 31;
            sh_bc[i][j] = pbase[(size_t)(t0 + i) * 96 + j];
        }
        __syncthreads();
#pragma unroll 4
        for (int i = 0; i < 32; i++) {
            float dlt = sh_d[ch][i];
            float uu  = sh_u[ch][i];
            float du  = dlt * uu;
            float4 b4 = *(const float4*)&sh_bc[i][q * 4];
            float4 c4 = *(const float4*)&sh_bc[i][16 + q * 4];
            float e0 = __expf(dlt * a0);
            float e1 = __expf(dlt * a1);
            float e2 = __expf(dlt * a2);
            float e3 = __expf(dlt * a3);
            s0 = e0 * s0 + du * b4.x;
            s1 = e1 * s1 + du * b4.y;
            s2 = e2 * s2 + du * b4.z;
            s3 = e3 * s3 + du * b4.w;
            float acc = s0 * c4.x + s1 * c4.y + s2 * c4.z + s3 * c4.w;
            acc += __shfl_xor_sync(0xffffffffu, acc, 1);
            acc += __shfl_xor_sync(0xffffffffu, acc, 2);
            if (q == 0)
                ybase[(size_t)(t0 + i) * DI + w * 8 + chw] = acc + uu * dpv;
        }
        __syncthreads();
    }
}

// ---------------- launch ----------------
extern "C" void kernel_launch(void* const* d_in, const int* in_sizes, int n_in,
                              void* d_out, int out_size)
{
    (void)in_sizes; (void)n_in; (void)out_size;
    const float* x     = (const float*)d_in[0];
    const float* Win   = (const float*)d_in[1];
    const float* Wconv = (const float*)d_in[2];
    const float* bconv = (const float*)d_in[3];
    const float* Wx    = (const float*)d_in[4];
    const float* Wdt   = (const float*)d_in[5];
    const float* bdt   = (const float*)d_in[6];
    const float* A_log = (const float*)d_in[7];
    const float* Dp    = (const float*)d_in[8];
    const float* Wout  = (const float*)d_in[9];
    float* out = (float*)d_out;

    cudaFuncSetAttribute(mma_gemm_kernel<1>, cudaFuncAttributeMaxDynamicSharedMemorySize, GSMEM_B);
    cudaFuncSetAttribute(mma_gemm_kernel<3>, cudaFuncAttributeMaxDynamicSharedMemorySize, GSMEM_B);

    convert_x_kernel<<<4096, 256>>>(x);                                 // x -> A1 fp16
    transpose_convert_kernel<1><<<dim3(128, 32), dim3(32, 8)>>>(Win);   // Win^T fp16
    mma_gemm_kernel<1><<<dim3(32, 32), 256, GSMEM_B>>>(nullptr);        // g_xz = x@Win
    conv_kernel<<<dim3(SS / 32, DI / 32, BB), 256>>>(Wconv, bconv);
    gemm_params_kernel<<<dim3(MM / 64), 256>>>(Wx);
    gemm_delta_kernel<<<dim3(MM / 32, DI / 64), 256>>>(Wdt, bdt);
    scan_kernel<<<dim3(BB * DI / 16), 64>>>(A_log, Dp);
    gate_convert_kernel<<<8192, 256>>>();                               // y*silu(z) -> A3 fp16
    transpose_convert_kernel<3><<<dim3(32, 64), dim3(32, 8)>>>(Wout);   // Wout^T fp16
    mma_gemm_kernel<3><<<dim3(8, 32), 256, GSMEM_B>>>(out);             // out = A3@Wout
}

// round 6
// speedup vs baseline: 3.2059x; 1.1225x over previous
#include <cuda_runtime.h>
#include <cuda_fp16.h>
#include <math.h>
#include <stdint.h>

#define BB 2
#define SS 2048
#define DM 1024
#define DI 2048
#define DSTATE 16
#define RANK 64
#define MM (BB*SS)   /* 4096 rows (b,s) */

// ---------------- scratch (static device globals; no runtime allocation) ----------------
__device__ float g_xz[(size_t)MM * 2 * DI];     // [m][4096]  x@Win
__device__ float g_xbc[(size_t)MM * DI];        // conv+silu (u), [m][d]
__device__ __half g_xbch[(size_t)MM * DI];      // fp16 copy for params mma
__device__ float g_params[(size_t)MM * 96];     // [m][96]  (delta_in | b | c)
__device__ __half g_dinh[(size_t)MM * RANK];    // fp16 delta_in for delta mma
__device__ float g_delta[(size_t)MM * DI];      // softplus delta, [m][d]
__device__ float g_y[(size_t)MM * DI];          // scan output, [m][d]

// fp16 operands for tensor-core GEMMs
__device__ __half g_A1h[(size_t)MM * DM];
__device__ __half g_B1h[(size_t)(2*DI) * DM];   // Win^T [N=4096][K=1024]
__device__ __half g_A3h[(size_t)MM * DI];       // gated y [4096][2048]
__device__ __half g_B3h[(size_t)DM * DI];       // Wout^T [N=1024][K=2048]
__device__ __half g_Wxh[(size_t)96 * DI];       // Wx^T  [96][2048]
__device__ __half g_Wdth[(size_t)DI * RANK];    // Wdt^T [2048][64]

// ================= low-level helpers (baseline PTX only: sm_80-class) =================
__device__ __forceinline__ uint32_t smem_to_u32(const void* smem_ptr) {
    uint32_t addr;
    asm("{ .reg .u64 tmp; cvta.to.shared.u64 tmp, %1; cvt.u32.u64 %0, tmp; }"
        : "=r"(addr) : "l"(smem_ptr));
    return addr;
}
#define CP_ASYNC16(saddr, gaddr) \
    asm volatile("cp.async.cg.shared.global [%0], [%1], 16;" :: "r"(saddr), "l"(gaddr))
#define CP_COMMIT() asm volatile("cp.async.commit_group;" ::: "memory")
#define CP_WAIT(n)  asm volatile("cp.async.wait_group %0;" :: "n"(n) : "memory")

__device__ __forceinline__ void ldsm4(uint32_t* r, uint32_t addr) {
    asm volatile("ldmatrix.sync.aligned.m8n8.x4.shared.b16 {%0,%1,%2,%3}, [%4];"
        : "=r"(r[0]), "=r"(r[1]), "=r"(r[2]), "=r"(r[3]) : "r"(addr));
}
__device__ __forceinline__ void mma16816(float* d, const uint32_t* a, const uint32_t* b) {
    asm volatile(
        "mma.sync.aligned.m16n8k16.row.col.f32.f16.f16.f32 "
        "{%0,%1,%2,%3}, {%4,%5,%6,%7}, {%8,%9}, {%0,%1,%2,%3};"
        : "+f"(d[0]), "+f"(d[1]), "+f"(d[2]), "+f"(d[3])
        : "r"(a[0]), "r"(a[1]), "r"(a[2]), "r"(a[3]), "r"(b[0]), "r"(b[1]));
}

// ================= convert / transpose kernels =================
__global__ void convert_x_kernel(const float* __restrict__ src)   // -> g_A1h
{
    int i = blockIdx.x * 256 + threadIdx.x;
    float4 v = ((const float4*)src)[i];
    __half2 p0 = __floats2half2_rn(v.x, v.y);
    __half2 p1 = __floats2half2_rn(v.z, v.w);
    uint2 ph = make_uint2(*(uint32_t*)&p0, *(uint32_t*)&p1);
    *(uint2*)&g_A1h[(size_t)i*4] = ph;
}

__global__ void gate_convert_kernel()   // A3 = g_y * silu(z) -> g_A3h
{
    int i = blockIdx.x * 256 + threadIdx.x;
    int e = i * 4;
    int m = e >> 11;
    int k = e & 2047;
    float4 y4 = *(const float4*)&g_y[(size_t)m * DI + k];
    float4 z4 = *(const float4*)&g_xz[(size_t)m * (2*DI) + DI + k];
    float a0 = y4.x * z4.x / (1.f + __expf(-z4.x));
    float a1 = y4.y * z4.y / (1.f + __expf(-z4.y));
    float a2 = y4.z * z4.z / (1.f + __expf(-z4.z));
    float a3 = y4.w * z4.w / (1.f + __expf(-z4.w));
    __half2 p0 = __floats2half2_rn(a0, a1);
    __half2 p1 = __floats2half2_rn(a2, a3);
    uint2 ph = make_uint2(*(uint32_t*)&p0, *(uint32_t*)&p1);
    *(uint2*)&g_A3h[(size_t)e] = ph;
}

// generic: src [KD][ND] row-major -> dst [ND][KD] fp16
template<int ND, int KD>
__global__ void transpose_convert_kernel(const float* __restrict__ src, __half* __restrict__ dst)
{
    __shared__ float t[32][33];
    int n0 = blockIdx.x * 32, k0 = blockIdx.y * 32;
    int tx = threadIdx.x, ty = threadIdx.y;
#pragma unroll
    for (int i = 0; i < 4; i++)
        t[ty + i*8][tx] = src[(size_t)(k0 + ty + i*8) * ND + n0 + tx];
    __syncthreads();
#pragma unroll
    for (int i = 0; i < 4; i++) {
        int n = n0 + ty + i*8, k = k0 + tx;
        dst[(size_t)n * KD + k] = __float2half_rn(t[tx][ty + i*8]);
    }
}

// ================= main mma.sync GEMM (unchanged from R5) =================
static constexpr int TSTRIDE = 40;
static constexpr uint32_t TILE_B = 128 * TSTRIDE * 2;
static constexpr uint32_t STAGE_B = 2 * TILE_B;
static constexpr uint32_t GSMEM_B = 3 * STAGE_B;

__device__ __forceinline__ void load_tile_ca(uint32_t sbase, const __half* g,
                                             int row0, int ktot, int kbase, int tid)
{
#pragma unroll
    for (int it = 0; it < 2; it++) {
        int u = tid + it * 256;
        int r = u >> 2, seg = u & 3;
        uint32_t s = sbase + (uint32_t)(r * TSTRIDE + seg * 8) * 2;
        const __half* gp = g + (size_t)(row0 + r) * ktot + kbase + seg * 8;
        CP_ASYNC16(s, gp);
    }
}

template<int WHICH>
__global__ __launch_bounds__(256, 2)
void mma_gemm_kernel(float* __restrict__ Cout)
{
    constexpr int KTOT = (WHICH == 1) ? DM : DI;
    constexpr int NC = KTOT / 32;
    constexpr int LDC = (WHICH == 1) ? (2*DI) : DM;
    const __half* Ah = (WHICH == 1) ? g_A1h : g_A3h;
    const __half* Bh = (WHICH == 1) ? g_B1h : g_B3h;

    extern __shared__ __align__(16) char smem[];
    uint32_t sb = smem_to_u32(smem);

    int tid = threadIdx.x;
    int lane = tid & 31, wid = tid >> 5;
    int wm = wid & 3;
    int wn = wid >> 2;
    int m0 = blockIdx.y * 128;
    int n0 = blockIdx.x * 128;

    float d[2][8][4];
#pragma unroll
    for (int mt = 0; mt < 2; mt++)
#pragma unroll
        for (int nt = 0; nt < 8; nt++)
#pragma unroll
            for (int i = 0; i < 4; i++) d[mt][nt][i] = 0.f;

    const uint32_t OA = 0, OB = TILE_B;

#pragma unroll
    for (int p = 0; p < 2; p++) {
        uint32_t base = sb + p * STAGE_B;
        int kb = p * 32;
        load_tile_ca(base + OA, Ah, m0, KTOT, kb, tid);
        load_tile_ca(base + OB, Bh, n0, KTOT, kb, tid);
        CP_COMMIT();
    }

    int quad = lane >> 3, lrow = lane & 7;
    int st = 0;

    for (int kc = 0; kc < NC; kc++) {
        if (kc + 1 < NC) CP_WAIT(1); else CP_WAIT(0);
        __syncthreads();

        if (kc + 2 < NC) {
            int pst = st + 2; if (pst >= 3) pst -= 3;
            uint32_t base = sb + pst * STAGE_B;
            int kb = (kc + 2) * 32;
            load_tile_ca(base + OA, Ah, m0, KTOT, kb, tid);
            load_tile_ca(base + OB, Bh, n0, KTOT, kb, tid);
            CP_COMMIT();
        }

        uint32_t base = sb + st * STAGE_B;
#pragma unroll
        for (int ks = 0; ks < 2; ks++) {
            int k16 = ks * 16;
            uint32_t aH[2][4];
#pragma unroll
            for (int mt = 0; mt < 2; mt++) {
                int row = wm * 32 + mt * 16 + (quad & 1) * 8 + lrow;
                uint32_t off = (uint32_t)(row * TSTRIDE + k16 + (quad >> 1) * 8) * 2;
                ldsm4(aH[mt], base + OA + off);
            }
            uint32_t bH[8][2];
#pragma unroll
            for (int np = 0; np < 4; np++) {
                int nrow = wn * 64 + np * 16 + (quad >> 1) * 8 + lrow;
                uint32_t off = (uint32_t)(nrow * TSTRIDE + k16 + (quad & 1) * 8) * 2;
                uint32_t t[4];
                ldsm4(t, base + OB + off);
                bH[np*2][0] = t[0]; bH[np*2][1] = t[1];
                bH[np*2+1][0] = t[2]; bH[np*2+1][1] = t[3];
            }
#pragma unroll
            for (int mt = 0; mt < 2; mt++)
#pragma unroll
                for (int nt = 0; nt < 8; nt++)
                    mma16816(d[mt][nt], aH[mt], bH[nt]);
        }
        __syncthreads();
        st++; if (st >= 3) st -= 3;
    }

    float* C = (WHICH == 1) ? g_xz : Cout;
#pragma unroll
    for (int mt = 0; mt < 2; mt++)
#pragma unroll
        for (int nt = 0; nt < 8; nt++) {
            int row = m0 + wm * 32 + mt * 16 + (lane >> 2);
            int col = n0 + wn * 64 + nt * 8 + (lane & 3) * 2;
            float2 v0 = {d[mt][nt][0], d[mt][nt][1]};
            float2 v1 = {d[mt][nt][2], d[mt][nt][3]};
            *(float2*)&C[(size_t)row * LDC + col] = v0;
            *(float2*)&C[(size_t)(row + 8) * LDC + col] = v1;
        }
}

// ---------------- conv: depthwise causal K=4 + bias + silu -> g_xbc (f32) + g_xbch (f16) ----------------
__global__ __launch_bounds__(256)
void conv_kernel(const float* __restrict__ Wconv, const float* __restrict__ bconv)
{
    __shared__ float sh_x[35][33];
    __shared__ float sh_w[4][32];
    __shared__ float sh_b[32];
    int tid = threadIdx.x;
    int b  = blockIdx.z;
    int d0 = blockIdx.y * 32;
    int s0 = blockIdx.x * 32;

    for (int idx = tid; idx < 35 * 32; idx += 256) {
        int r = idx >> 5, c = idx & 31;
        int s = s0 - 3 + r;
        float v = 0.f;
        if (s >= 0)
            v = g_xz[((size_t)(b * SS + s)) * (2 * DI) + d0 + c];
        sh_x[r][c] = v;
    }
    if (tid < 128) {
        int k = tid >> 5, c = tid & 31;
        sh_w[k][c] = Wconv[(size_t)(d0 + c) * 4 + k];
    }
    if (tid < 32) sh_b[tid] = bconv[d0 + tid];
    __syncthreads();

    int td = tid & 31, tg = tid >> 5;
#pragma unroll
    for (int si = 0; si < 4; si++) {
        int ss = tg + si * 8;
        float o = sh_b[td]
                + sh_x[ss + 0][td] * sh_w[0][td]
                + sh_x[ss + 1][td] * sh_w[1][td]
                + sh_x[ss + 2][td] * sh_w[2][td]
                + sh_x[ss + 3][td] * sh_w[3][td];
        o = o / (1.f + __expf(-o));
        size_t off = ((size_t)(b * SS + s0 + ss)) * DI + d0 + td;
        g_xbc[off]  = o;
        g_xbch[off] = __float2half_rn(o);
    }
}

// ---------------- params mma: g_params[m][96] = xbc @ Wx ; also fp16 delta_in copy ----------------
static constexpr int PTS = 72;   // padded k stride (fp16 elems) for k-chunk 64
__global__ __launch_bounds__(128)
void params_mma_kernel()
{
    // block: 64 rows x 96 cols; 4 warps (2m x 2n), warp tile 32x48; K chunks of 64
    __shared__ __align__(16) char ps[2 * (64 + 96) * PTS * 2];
    const uint32_t ST = (64 + 96) * PTS * 2;   // 23040 B per stage
    const uint32_t OB = 64 * PTS * 2;          // B tile after 64 A rows
    uint32_t sb = smem_to_u32(ps);

    int tid = threadIdx.x;
    int lane = tid & 31, wid = tid >> 5;
    int wm = wid & 1, wn = wid >> 1;
    int m0 = blockIdx.x * 64;

    float d[2][6][4];
#pragma unroll
    for (int mt = 0; mt < 2; mt++)
#pragma unroll
        for (int nt = 0; nt < 6; nt++)
#pragma unroll
            for (int i = 0; i < 4; i++) d[mt][nt][i] = 0.f;

    auto load_stage = [&](int stg, int kb) {
        uint32_t base = sb + stg * ST;
#pragma unroll
        for (int it = 0; it < 4; it++) {           // A: 64 rows x 64k
            int u = tid + it * 128;
            int r = u >> 3, c8 = u & 7;
            CP_ASYNC16(base + (uint32_t)(r * PTS + c8 * 8) * 2,
                       g_xbch + (size_t)(m0 + r) * DI + kb + c8 * 8);
        }
#pragma unroll
        for (int it = 0; it < 6; it++) {           // B: 96 rows x 64k
            int u = tid + it * 128;
            int r = u >> 3, c8 = u & 7;
            CP_ASYNC16(base + OB + (uint32_t)(r * PTS + c8 * 8) * 2,
                       g_Wxh + (size_t)r * DI + kb + c8 * 8);
        }
        CP_COMMIT();
    };

    load_stage(0, 0);
    int quad = lane >> 3, lrow = lane & 7;
    const int NC = DI / 64;   // 32

    for (int kc = 0; kc < NC; kc++) {
        if (kc + 1 < NC) { load_stage((kc + 1) & 1, (kc + 1) * 64); CP_WAIT(1); }
        else CP_WAIT(0);
        __syncthreads();
        uint32_t base = sb + (kc & 1) * ST;
#pragma unroll
        for (int ks = 0; ks < 4; ks++) {
            int k16 = ks * 16;
            uint32_t aH[2][4];
#pragma unroll
            for (int mt = 0; mt < 2; mt++) {
                int row = wm * 32 + mt * 16 + (quad & 1) * 8 + lrow;
                ldsm4(aH[mt], base + (uint32_t)(row * PTS + k16 + (quad >> 1) * 8) * 2);
            }
            uint32_t bH[6][2];
#pragma unroll
            for (int np = 0; np < 3; np++) {
                int nrow = wn * 48 + np * 16 + (quad >> 1) * 8 + lrow;
                uint32_t t[4];
                ldsm4(t, base + OB + (uint32_t)(nrow * PTS + k16 + (quad & 1) * 8) * 2);
                bH[np*2][0] = t[0]; bH[np*2][1] = t[1];
                bH[np*2+1][0] = t[2]; bH[np*2+1][1] = t[3];
            }
#pragma unroll
            for (int mt = 0; mt < 2; mt++)
#pragma unroll
                for (int nt = 0; nt < 6; nt++)
                    mma16816(d[mt][nt], aH[mt], bH[nt]);
        }
        __syncthreads();
    }

#pragma unroll
    for (int mt = 0; mt < 2; mt++)
#pragma unroll
        for (int nt = 0; nt < 6; nt++) {
            int row = m0 + wm * 32 + mt * 16 + (lane >> 2);
            int col = wn * 48 + nt * 8 + (lane & 3) * 2;
            float2 v0 = {d[mt][nt][0], d[mt][nt][1]};
            float2 v1 = {d[mt][nt][2], d[mt][nt][3]};
            *(float2*)&g_params[(size_t)row * 96 + col] = v0;
            *(float2*)&g_params[(size_t)(row + 8) * 96 + col] = v1;
            if (col < 64) {
                __half2 h0 = __floats2half2_rn(v0.x, v0.y);
                __half2 h1 = __floats2half2_rn(v1.x, v1.y);
                *(__half2*)&g_dinh[(size_t)row * 64 + col] = h0;
                *(__half2*)&g_dinh[(size_t)(row + 8) * 64 + col] = h1;
            }
        }
}

// ---------------- delta mma: g_delta[m][d] = softplus(delta_in @ Wdt + bdt) ----------------
__global__ __launch_bounds__(256)
void delta_mma_kernel(const float* __restrict__ bdt)
{
    // block 128m x 128n, 8 warps 32x64, K=64 single shot
    __shared__ __align__(16) char ds[2 * 128 * PTS * 2];
    const uint32_t OB = 128 * PTS * 2;
    uint32_t sb = smem_to_u32(ds);

    int tid = threadIdx.x;
    int lane = tid & 31, wid = tid >> 5;
    int wm = wid & 3, wn = wid >> 2;
    int n0 = blockIdx.x * 128;
    int m0 = blockIdx.y * 128;

#pragma unroll
    for (int it = 0; it < 4; it++) {               // A: 128 rows x 64k
        int u = tid + it * 256;
        int r = u >> 3, c8 = u & 7;
        CP_ASYNC16(sb + (uint32_t)(r * PTS + c8 * 8) * 2,
                   g_dinh + (size_t)(m0 + r) * 64 + c8 * 8);
    }
#pragma unroll
    for (int it = 0; it < 4; it++) {               // B: 128 n-rows x 64k
        int u = tid + it * 256;
        int r = u >> 3, c8 = u & 7;
        CP_ASYNC16(sb + OB + (uint32_t)(r * PTS + c8 * 8) * 2,
                   g_Wdth + (size_t)(n0 + r) * 64 + c8 * 8);
    }
    CP_COMMIT();

    float d[2][8][4];
#pragma unroll
    for (int mt = 0; mt < 2; mt++)
#pragma unroll
        for (int nt = 0; nt < 8; nt++)
#pragma unroll
            for (int i = 0; i < 4; i++) d[mt][nt][i] = 0.f;

    CP_WAIT(0);
    __syncthreads();

    int quad = lane >> 3, lrow = lane & 7;
#pragma unroll
    for (int ks = 0; ks < 4; ks++) {
        int k16 = ks * 16;
        uint32_t aH[2][4];
#pragma unroll
        for (int mt = 0; mt < 2; mt++) {
            int row = wm * 32 + mt * 16 + (quad & 1) * 8 + lrow;
            ldsm4(aH[mt], sb + (uint32_t)(row * PTS + k16 + (quad >> 1) * 8) * 2);
        }
        uint32_t bH[8][2];
#pragma unroll
        for (int np = 0; np < 4; np++) {
            int nrow = wn * 64 + np * 16 + (quad >> 1) * 8 + lrow;
            uint32_t t[4];
            ldsm4(t, sb + OB + (uint32_t)(nrow * PTS + k16 + (quad & 1) * 8) * 2);
            bH[np*2][0] = t[0]; bH[np*2][1] = t[1];
            bH[np*2+1][0] = t[2]; bH[np*2+1][1] = t[3];
        }
#pragma unroll
        for (int mt = 0; mt < 2; mt++)
#pragma unroll
            for (int nt = 0; nt < 8; nt++)
                mma16816(d[mt][nt], aH[mt], bH[nt]);
    }

#pragma unroll
    for (int mt = 0; mt < 2; mt++)
#pragma unroll
        for (int nt = 0; nt < 8; nt++) {
            int row = m0 + wm * 32 + mt * 16 + (lane >> 2);
            int col = n0 + wn * 64 + nt * 8 + (lane & 3) * 2;
            float b0 = bdt[col], b1 = bdt[col + 1];
#pragma unroll
            for (int h = 0; h < 2; h++) {
                float t0 = d[mt][nt][h*2+0] + b0;
                float t1 = d[mt][nt][h*2+1] + b1;
                float2 v;
                v.x = fmaxf(t0, 0.f) + log1pf(__expf(-fabsf(t0)));
                v.y = fmaxf(t1, 0.f) + log1pf(__expf(-fabsf(t1)));
                *(float2*)&g_delta[(size_t)(row + h*8) * DI + col] = v;
            }
        }
}

// ---------------- selective scan: 8 lanes/channel, 2 states/lane ----------------
__global__ __launch_bounds__(128, 8)
void scan_kernel(const float* __restrict__ A_log, const float* __restrict__ Dp)
{
    __shared__ float2 sh_duu[32][16];   // (delta, u) per (step, ch)
    __shared__ float  sh_bc[32][32];    // b[0..15] c[0..15]
    __shared__ float  sh_y[32][16];
    int tid = threadIdx.x;
    int lane = tid & 31, w = tid >> 5;          // 4 warps
    int gch0 = blockIdx.x * 16;
    int b  = gch0 / DI;
    int d0 = gch0 % DI;
    int q  = lane & 7;                          // states 2q, 2q+1
    int ch = w * 4 + (lane >> 3);               // 0..15
    int d  = d0 + ch;

    float an0, an1;
    {
        float2 al = *(const float2*)&A_log[(size_t)d * DSTATE + 2 * q];
        an0 = -__expf(al.x) * 1.44269504f;
        an1 = -__expf(al.y) * 1.44269504f;
    }
    float dpv = Dp[d];
    float s0 = 0.f, s1 = 0.f;

    const float* dmb = g_delta + (size_t)b * SS * DI + d0;
    const float* umb = g_xbc  + (size_t)b * SS * DI + d0;
    const float* pmb = g_params + (size_t)b * SS * 96 + 64;
    float* ymb = g_y + (size_t)b * SS * DI + d0;

    for (int t0 = 0; t0 < SS; t0 += 32) {
#pragma unroll
        for (int k = 0; k < 4; k++) {
            int idx = tid + k * 128;
            int i = idx >> 4, j = idx & 15;
            size_t off = (size_t)(t0 + i) * DI + j;
            sh_duu[i][j] = make_float2(dmb[off], umb[off]);
        }
#pragma unroll
        for (int k = 0; k < 8; k++) {
            int idx = tid + k * 128;
            int i = idx >> 5, j = idx & 31;
            sh_bc[i][j] = pmb[(size_t)(t0 + i) * 96 + j];
        }
        __syncthreads();

#pragma unroll 4
        for (int i = 0; i < 32; i++) {
            float2 duu = sh_duu[i][ch];
            float2 bq = *(float2*)&sh_bc[i][2 * q];
            float2 cq = *(float2*)&sh_bc[i][16 + 2 * q];
            float du = duu.x * duu.y;
            float e0 = exp2f(duu.x * an0);
            float e1 = exp2f(duu.x * an1);
            s0 = fmaf(e0, s0, du * bq.x);
            s1 = fmaf(e1, s1, du * bq.y);
            float acc = fmaf(s1, cq.y, s0 * cq.x);
            acc += __shfl_xor_sync(0xffffffffu, acc, 1);
            acc += __shfl_xor_sync(0xffffffffu, acc, 2);
            acc += __shfl_xor_sync(0xffffffffu, acc, 4);
            if (q == 0) sh_y[i][ch] = fmaf(duu.y, dpv, acc);
        }
        __syncthreads();
#pragma unroll
        for (int k = 0; k < 4; k++) {
            int idx = tid + k * 128;
            int i = idx >> 4, j = idx & 15;
            ymb[(size_t)(t0 + i) * DI + j] = sh_y[i][j];
        }
    }
}

// ---------------- launch ----------------
extern "C" void kernel_launch(void* const* d_in, const int* in_sizes, int n_in,
                              void* d_out, int out_size)
{
    (void)in_sizes; (void)n_in; (void)out_size;
    const float* x     = (const float*)d_in[0];
    const float* Win   = (const float*)d_in[1];
    const float* Wconv = (const float*)d_in[2];
    const float* bconv = (const float*)d_in[3];
    const float* Wx    = (const float*)d_in[4];
    const float* Wdt   = (const float*)d_in[5];
    const float* bdt   = (const float*)d_in[6];
    const float* A_log = (const float*)d_in[7];
    const float* Dp    = (const float*)d_in[8];
    const float* Wout  = (const float*)d_in[9];
    float* out = (float*)d_out;

    __half *pB1h = nullptr, *pB3h = nullptr, *pWxh = nullptr, *pWdth = nullptr;
    cudaGetSymbolAddress((void**)&pB1h, g_B1h);
    cudaGetSymbolAddress((void**)&pB3h, g_B3h);
    cudaGetSymbolAddress((void**)&pWxh, g_Wxh);
    cudaGetSymbolAddress((void**)&pWdth, g_Wdth);

    cudaFuncSetAttribute(mma_gemm_kernel<1>, cudaFuncAttributeMaxDynamicSharedMemorySize, GSMEM_B);
    cudaFuncSetAttribute(mma_gemm_kernel<3>, cudaFuncAttributeMaxDynamicSharedMemorySize, GSMEM_B);

    convert_x_kernel<<<4096, 256>>>(x);
    transpose_convert_kernel<4096, 1024><<<dim3(128, 32), dim3(32, 8)>>>(Win, pB1h);
    mma_gemm_kernel<1><<<dim3(32, 32), 256, GSMEM_B>>>(nullptr);            // g_xz = x@Win
    conv_kernel<<<dim3(SS / 32, DI / 32, BB), 256>>>(Wconv, bconv);
    transpose_convert_kernel<96, 2048><<<dim3(3, 64), dim3(32, 8)>>>(Wx, pWxh);
    params_mma_kernel<<<64, 128>>>();
    transpose_convert_kernel<2048, 64><<<dim3(64, 2), dim3(32, 8)>>>(Wdt, pWdth);
    delta_mma_kernel<<<dim3(16, 32), 256>>>(bdt);
    scan_kernel<<<256, 128>>>(A_log, Dp);
    gate_convert_kernel<<<8192, 256>>>();
    transpose_convert_kernel<1024, 2048><<<dim3(32, 64), dim3(32, 8)>>>(Wout, pB3h);
    mma_gemm_kernel<3><<<dim3(8, 32), 256, GSMEM_B>>>(out);                 // out = A3@Wout
}